// round 2
// baseline (speedup 1.0000x reference)
#include <cuda_runtime.h>
#include <cstdint>
#include <cstddef>

#define Nn 100000
#define Ee 500000
#define Dd 128
#define Ll 5

// -------- scratch (device globals: allocation-free) --------
__device__ __align__(16) float g_h[(size_t)Nn * 128];
__device__ __align__(16) float g_agg[(size_t)Nn * 128];
__device__ __align__(16) float g_t1[(size_t)Nn * 256];
__device__ __align__(16) float g_t2[(size_t)Nn * 128];
__device__ float g_stats1[512];   // 256 sums, 256 sumsq
__device__ float g_stats2[256];   // 128 sums, 128 sumsq
__device__ float g_sc1[512];      // 256 scale, 256 shift
__device__ float g_sc2[256];      // 128 scale, 128 shift

// -------- packed f32x2 helpers (FFMA2 path: 2x fp32 FMA throughput) --------
__device__ __forceinline__ unsigned long long bcast2(float a) {
    unsigned long long r;
    asm("mov.b64 %0, {%1, %1};" : "=l"(r) : "f"(a));
    return r;
}
__device__ __forceinline__ void ffma2(unsigned long long& d,
                                      unsigned long long a,
                                      unsigned long long b) {
    asm("fma.rn.f32x2 %0, %1, %2, %0;" : "+l"(d) : "l"(a), "l"(b));
}
__device__ __forceinline__ float2 unpack2(unsigned long long v) {
    float2 f;
    asm("mov.b64 {%0, %1}, %2;" : "=f"(f.x), "=f"(f.y) : "l"(v));
    return f;
}

// -------- h init: h[n,d] = sum_f atom_emb[f, x[n,f], d] --------
__global__ void init_h_kernel(const int* __restrict__ x,
                              const float* __restrict__ ae,
                              float* __restrict__ h) {
    int idx = blockIdx.x * blockDim.x + threadIdx.x;
    if (idx >= Nn * 128) return;
    int n = idx >> 7, d = idx & 127;
    float s = 0.f;
#pragma unroll
    for (int f = 0; f < 9; f++) {
        int xi = __ldg(x + n * 9 + f);
        s += __ldg(ae + (((size_t)(f * 120 + xi)) << 7) + d);
    }
    h[idx] = s;
}

// -------- edge kernel: agg[dst] += relu(h[src] + bond_e) * ew --------
__global__ void __launch_bounds__(256) edge_kernel(
    const float* __restrict__ h, const float* __restrict__ be,
    const int* __restrict__ ei, const int* __restrict__ ea,
    const float* __restrict__ ew, float* __restrict__ agg)
{
    __shared__ __align__(16) float sbe[3 * 8 * 128];   // bond_emb for this layer (12KB)
    for (int i = threadIdx.x; i < 3 * 8 * 128; i += 256) sbe[i] = be[i];
    __syncthreads();

    int gwarp = (blockIdx.x * 256 + threadIdx.x) >> 5;
    int lane  = threadIdx.x & 31;
    int nw    = (gridDim.x * 256) >> 5;
    int d0    = lane * 4;

    for (int e = gwarp; e < Ee; e += nw) {
        int src = __ldg(ei + e);
        int dst = __ldg(ei + Ee + e);
        int a0  = __ldg(ea + e * 3 + 0);
        int a1  = __ldg(ea + e * 3 + 1);
        int a2  = __ldg(ea + e * 3 + 2);
        float w = __ldg(ew + e);

        const float4 hv = *(const float4*)(h + (size_t)src * 128 + d0);
        const float4 e0 = *(const float4*)(sbe + (a0      ) * 128 + d0);
        const float4 e1 = *(const float4*)(sbe + (8  + a1 ) * 128 + d0);
        const float4 e2 = *(const float4*)(sbe + (16 + a2 ) * 128 + d0);

        float m0 = fmaxf(hv.x + e0.x + e1.x + e2.x, 0.f) * w;
        float m1 = fmaxf(hv.y + e0.y + e1.y + e2.y, 0.f) * w;
        float m2 = fmaxf(hv.z + e0.z + e1.z + e2.z, 0.f) * w;
        float m3 = fmaxf(hv.w + e0.w + e1.w + e2.w, 0.f) * w;

        float* p = agg + (size_t)dst * 128 + d0;
        asm volatile("red.global.add.v4.f32 [%0], {%1,%2,%3,%4};"
                     :: "l"(p), "f"(m0), "f"(m1), "f"(m2), "f"(m3) : "memory");
    }
}

// -------- GEMM: C[M,NC] = X @ W + bias, + per-column sum/sumsq stats --------
// MODE 0: X = (1+eps[layer])*A + A2            (z build fused; K=128, NC=256)
// MODE 1: X = relu(sc[k]*A + sh[k])            (BN1+ReLU fused; K=256, NC=128)
// Inner product uses packed fma.rn.f32x2 (FFMA2) for 2x fp32 throughput.
template <int MODE>
__global__ void __launch_bounds__(256) gemm_kernel(
    const float* __restrict__ A, const float* __restrict__ A2,
    const float* __restrict__ epsp, int layer,
    const float* __restrict__ scsh,
    const float* __restrict__ W, const float* __restrict__ bias,
    float* __restrict__ C, float* __restrict__ stats,
    int M, int K, int NC)
{
    __shared__ __align__(16) float As[16][132];
    __shared__ __align__(16) float Ws[16][128];
    __shared__ float s_sum[128];
    __shared__ float s_sq[128];

    const int tid = threadIdx.x;
    const int tx = tid & 15, ty = tid >> 4;
    const int rowBase = blockIdx.x * 128;
    const int colBase = blockIdx.y * 128;

    float alpha = 1.0f;
    if (MODE == 0) alpha = 1.0f + __ldg(epsp + layer);
    const float* shv = (MODE == 1) ? (scsh + K) : (const float*)nullptr;

    unsigned long long acc2[8][4];
#pragma unroll
    for (int i = 0; i < 8; i++)
#pragma unroll
        for (int j = 0; j < 4; j++) acc2[i][j] = 0ULL;

    for (int k0 = 0; k0 < K; k0 += 16) {
        // ---- A tile (transposed into shared), with fused transform ----
#pragma unroll
        for (int ld = 0; ld < 2; ld++) {
            int t  = tid + ld * 256;
            int r  = t >> 2;           // 0..127
            int kq = (t & 3) * 4;      // 0,4,8,12
            int rg = rowBase + r;
            float4 v = make_float4(0.f, 0.f, 0.f, 0.f);
            if (rg < M) {
                const float4 av = *(const float4*)(A + (size_t)rg * K + k0 + kq);
                if (MODE == 0) {
                    const float4 gv = *(const float4*)(A2 + (size_t)rg * K + k0 + kq);
                    v.x = fmaf(alpha, av.x, gv.x);
                    v.y = fmaf(alpha, av.y, gv.y);
                    v.z = fmaf(alpha, av.z, gv.z);
                    v.w = fmaf(alpha, av.w, gv.w);
                } else {
                    int kg = k0 + kq;
                    v.x = fmaxf(fmaf(__ldg(scsh + kg + 0), av.x, __ldg(shv + kg + 0)), 0.f);
                    v.y = fmaxf(fmaf(__ldg(scsh + kg + 1), av.y, __ldg(shv + kg + 1)), 0.f);
                    v.z = fmaxf(fmaf(__ldg(scsh + kg + 2), av.z, __ldg(shv + kg + 2)), 0.f);
                    v.w = fmaxf(fmaf(__ldg(scsh + kg + 3), av.w, __ldg(shv + kg + 3)), 0.f);
                }
            }
            As[kq + 0][r] = v.x;
            As[kq + 1][r] = v.y;
            As[kq + 2][r] = v.z;
            As[kq + 3][r] = v.w;
        }
        // ---- W tile ----
#pragma unroll
        for (int ld = 0; ld < 2; ld++) {
            int t  = tid + ld * 256;
            int kr = t >> 5;           // 0..15
            int c4 = (t & 31) * 4;     // 0..124
            *(float4*)&Ws[kr][c4] =
                *(const float4*)(W + (size_t)(k0 + kr) * NC + colBase + c4);
        }
        __syncthreads();

#pragma unroll
        for (int kk = 0; kk < 16; kk++) {
            float4 a0 = *(const float4*)&As[kk][ty * 8];
            float4 a1 = *(const float4*)&As[kk][ty * 8 + 4];
            ulonglong2 bb0 = *(const ulonglong2*)&Ws[kk][tx * 8];
            ulonglong2 bb1 = *(const ulonglong2*)&Ws[kk][tx * 8 + 4];
            unsigned long long b2[4] = {bb0.x, bb0.y, bb1.x, bb1.y};
            float a[8] = {a0.x, a0.y, a0.z, a0.w, a1.x, a1.y, a1.z, a1.w};
#pragma unroll
            for (int i = 0; i < 8; i++) {
                unsigned long long ab = bcast2(a[i]);
#pragma unroll
                for (int j = 0; j < 4; j++)
                    ffma2(acc2[i][j], ab, b2[j]);
            }
        }
        __syncthreads();
    }

    // ---- unpack accumulators ----
    float acc[8][8];
#pragma unroll
    for (int i = 0; i < 8; i++)
#pragma unroll
        for (int j = 0; j < 4; j++) {
            float2 f = unpack2(acc2[i][j]);
            acc[i][2 * j] = f.x;
            acc[i][2 * j + 1] = f.y;
        }

    // ---- epilogue: bias, store, column stats ----
    float bv[8];
#pragma unroll
    for (int j = 0; j < 8; j++) bv[j] = __ldg(bias + colBase + tx * 8 + j);
#pragma unroll
    for (int i = 0; i < 8; i++)
#pragma unroll
        for (int j = 0; j < 8; j++) acc[i][j] += bv[j];

    if (tid < 128) { s_sum[tid] = 0.f; s_sq[tid] = 0.f; }
    __syncthreads();

#pragma unroll
    for (int j = 0; j < 8; j++) {
        float cs = 0.f, cq = 0.f;
#pragma unroll
        for (int i = 0; i < 8; i++) {
            int rg = rowBase + ty * 8 + i;
            if (rg < M) { float v = acc[i][j]; cs += v; cq += v * v; }
        }
        atomicAdd(&s_sum[tx * 8 + j], cs);
        atomicAdd(&s_sq[tx * 8 + j], cq);
    }

#pragma unroll
    for (int i = 0; i < 8; i++) {
        int rg = rowBase + ty * 8 + i;
        if (rg < M) {
            float4 o0 = make_float4(acc[i][0], acc[i][1], acc[i][2], acc[i][3]);
            float4 o1 = make_float4(acc[i][4], acc[i][5], acc[i][6], acc[i][7]);
            *(float4*)(C + (size_t)rg * NC + colBase + tx * 8)     = o0;
            *(float4*)(C + (size_t)rg * NC + colBase + tx * 8 + 4) = o1;
        }
    }
    __syncthreads();
    if (tid < 128) {
        atomicAdd(&stats[colBase + tid],      s_sum[tid]);
        atomicAdd(&stats[NC + colBase + tid], s_sq[tid]);
    }
}

// -------- BN finalize: scale/shift from sums --------
__global__ void finalize_bn(const float* __restrict__ stats,
                            const float* __restrict__ g,
                            const float* __restrict__ bt,
                            float* __restrict__ scsh, int Cc) {
    int c = blockIdx.x * blockDim.x + threadIdx.x;
    if (c >= Cc) return;
    const float inv = 1.0f / (float)Nn;
    float mu  = stats[c] * inv;
    float var = stats[Cc + c] * inv - mu * mu;
    float sc  = __ldg(g + c) * rsqrtf(var + 1e-5f);
    scsh[c]      = sc;
    scsh[Cc + c] = fmaf(-mu, sc, __ldg(bt + c));
}

// -------- apply BN2 (+optional relu) --------
__global__ void apply_bn(const float* __restrict__ t2,
                         const float* __restrict__ scsh,
                         float* __restrict__ outp, int do_relu) {
    int idx = blockIdx.x * blockDim.x + threadIdx.x;
    if (idx >= Nn * 128) return;
    int c = idx & 127;
    float v = fmaf(scsh[c], t2[idx], scsh[128 + c]);
    outp[idx] = do_relu ? fmaxf(v, 0.f) : v;
}

extern "C" void kernel_launch(void* const* d_in, const int* in_sizes, int n_in,
                              void* d_out, int out_size) {
    const int*   x    = (const int*)d_in[0];
    const int*   ei   = (const int*)d_in[1];
    const int*   ea   = (const int*)d_in[2];
    const float* ew   = (const float*)d_in[3];
    const float* ae   = (const float*)d_in[4];
    const float* be   = (const float*)d_in[5];
    const float* eps  = (const float*)d_in[6];
    const float* W1   = (const float*)d_in[7];
    const float* b1   = (const float*)d_in[8];
    const float* g1   = (const float*)d_in[9];
    const float* bt1  = (const float*)d_in[10];
    const float* W2   = (const float*)d_in[11];
    const float* b2   = (const float*)d_in[12];
    const float* go   = (const float*)d_in[13];
    const float* bto  = (const float*)d_in[14];
    float* out = (float*)d_out;

    float *h, *agg, *t1, *t2, *st1, *st2, *sc1, *sc2;
    cudaGetSymbolAddress((void**)&h,   g_h);
    cudaGetSymbolAddress((void**)&agg, g_agg);
    cudaGetSymbolAddress((void**)&t1,  g_t1);
    cudaGetSymbolAddress((void**)&t2,  g_t2);
    cudaGetSymbolAddress((void**)&st1, g_stats1);
    cudaGetSymbolAddress((void**)&st2, g_stats2);
    cudaGetSymbolAddress((void**)&sc1, g_sc1);
    cudaGetSymbolAddress((void**)&sc2, g_sc2);

    const int elem_blocks = (Nn * 128 + 255) / 256;
    init_h_kernel<<<elem_blocks, 256>>>(x, ae, h);

    for (int l = 0; l < Ll; l++) {
        cudaMemsetAsync(agg, 0, (size_t)Nn * 128 * sizeof(float));
        cudaMemsetAsync(st1, 0, 512 * sizeof(float));
        cudaMemsetAsync(st2, 0, 256 * sizeof(float));

        edge_kernel<<<2048, 256>>>(h, be + (size_t)l * 3 * 8 * 128, ei, ea, ew, agg);

        dim3 grid1((Nn + 127) / 128, 2);
        gemm_kernel<0><<<grid1, 256>>>(h, agg, eps, l, (const float*)nullptr,
                                       W1 + (size_t)l * 128 * 256, b1 + l * 256,
                                       t1, st1, Nn, 128, 256);
        finalize_bn<<<1, 256>>>(st1, g1 + l * 256, bt1 + l * 256, sc1, 256);

        dim3 grid2((Nn + 127) / 128, 1);
        gemm_kernel<1><<<grid2, 256>>>(t1, (const float*)nullptr,
                                       (const float*)nullptr, 0, sc1,
                                       W2 + (size_t)l * 256 * 128, b2 + l * 128,
                                       t2, st2, Nn, 256, 128);
        finalize_bn<<<1, 128>>>(st2, go + l * 128, bto + l * 128, sc2, 128);

        float* dsth = (l == Ll - 1) ? out : h;
        apply_bn<<<elem_blocks, 256>>>(t2, sc2, dsth, (l < Ll - 1) ? 1 : 0);
    }
}

// round 6
// speedup vs baseline: 1.5921x; 1.5921x over previous
#include <cuda_runtime.h>
#include <cstdint>
#include <cstddef>

#define Nn 100000
#define Ee 500000
#define Ll 5

// -------- scratch (device globals: allocation-free) --------
__device__ __align__(16) float g_h[(size_t)Nn * 128];
__device__ __align__(16) float g_agg[(size_t)Nn * 128];
__device__ __align__(16) float g_t1[(size_t)Nn * 256];
__device__ __align__(16) float g_t2[(size_t)Nn * 128];
__device__ __align__(16) uint32_t g_wt1_hi[256 * 128];
__device__ __align__(16) uint32_t g_wt1_lo[256 * 128];
__device__ __align__(16) uint32_t g_wt2_hi[128 * 256];
__device__ __align__(16) uint32_t g_wt2_lo[128 * 256];
__device__ float g_stats1[512];
__device__ float g_stats2[256];
__device__ float g_sc1[512];
__device__ float g_sc2[256];

__device__ __forceinline__ uint32_t f2tf32(float v) {
    uint32_t o;
    asm("cvt.rna.tf32.f32 %0, %1;" : "=r"(o) : "f"(v));
    return o;
}
__device__ __forceinline__ void mma_tf32(float* c, const uint32_t* a, uint32_t b0, uint32_t b1) {
    asm volatile(
        "mma.sync.aligned.m16n8k8.row.col.f32.tf32.tf32.f32 "
        "{%0,%1,%2,%3}, {%4,%5,%6,%7}, {%8,%9}, {%0,%1,%2,%3};"
        : "+f"(c[0]), "+f"(c[1]), "+f"(c[2]), "+f"(c[3])
        : "r"(a[0]), "r"(a[1]), "r"(a[2]), "r"(a[3]), "r"(b0), "r"(b1));
}

// ======================= small kernels =======================
__global__ void init_h_kernel(const int* __restrict__ x,
                              const float* __restrict__ ae,
                              float* __restrict__ h) {
    int idx = blockIdx.x * blockDim.x + threadIdx.x;
    if (idx >= Nn * 128) return;
    int n = idx >> 7, d = idx & 127;
    float s = 0.f;
#pragma unroll
    for (int f = 0; f < 9; f++) {
        int xi = __ldg(x + n * 9 + f);
        s += __ldg(ae + (((size_t)(f * 120 + xi)) << 7) + d);
    }
    h[idx] = s;
}

__global__ void __launch_bounds__(256) edge_kernel(
    const float* __restrict__ h, const float* __restrict__ be,
    const int* __restrict__ ei, const int* __restrict__ ea,
    const float* __restrict__ ew, float* __restrict__ agg)
{
    __shared__ __align__(16) float sbe[3 * 8 * 128];
    for (int i = threadIdx.x; i < 3 * 8 * 128; i += 256) sbe[i] = be[i];
    __syncthreads();

    int gwarp = (blockIdx.x * 256 + threadIdx.x) >> 5;
    int lane  = threadIdx.x & 31;
    int nw    = (gridDim.x * 256) >> 5;
    int d0    = lane * 4;

    for (int e = gwarp; e < Ee; e += nw) {
        int src = __ldg(ei + e);
        int dst = __ldg(ei + Ee + e);
        int a0  = __ldg(ea + e * 3 + 0);
        int a1  = __ldg(ea + e * 3 + 1);
        int a2  = __ldg(ea + e * 3 + 2);
        float w = __ldg(ew + e);

        const float4 hv = *(const float4*)(h + (size_t)src * 128 + d0);
        const float4 e0 = *(const float4*)(sbe + (a0      ) * 128 + d0);
        const float4 e1 = *(const float4*)(sbe + (8  + a1 ) * 128 + d0);
        const float4 e2 = *(const float4*)(sbe + (16 + a2 ) * 128 + d0);

        float m0 = fmaxf(hv.x + e0.x + e1.x + e2.x, 0.f) * w;
        float m1 = fmaxf(hv.y + e0.y + e1.y + e2.y, 0.f) * w;
        float m2 = fmaxf(hv.z + e0.z + e1.z + e2.z, 0.f) * w;
        float m3 = fmaxf(hv.w + e0.w + e1.w + e2.w, 0.f) * w;

        float* p = agg + (size_t)dst * 128 + d0;
        asm volatile("red.global.add.v4.f32 [%0], {%1,%2,%3,%4};"
                     :: "l"(p), "f"(m0), "f"(m1), "f"(m2), "f"(m3) : "memory");
    }
}

// Wt_hi/lo[n*K + k] = split-tf32 of W[k*NC + n]
__global__ void transpose_w_kernel(const float* __restrict__ W,
                                   uint32_t* __restrict__ Wt_hi,
                                   uint32_t* __restrict__ Wt_lo, int K, int NC) {
    int idx = blockIdx.x * 256 + threadIdx.x;
    if (idx >= K * NC) return;
    int n = idx / K, k = idx - n * K;
    float w = __ldg(W + (size_t)k * NC + n);
    uint32_t hi = f2tf32(w);
    Wt_hi[idx] = hi;
    Wt_lo[idx] = f2tf32(w - __uint_as_float(hi));
}

__global__ void finalize_bn(const float* __restrict__ stats,
                            const float* __restrict__ g,
                            const float* __restrict__ bt,
                            float* __restrict__ scsh, int Cc) {
    int c = blockIdx.x * blockDim.x + threadIdx.x;
    if (c >= Cc) return;
    const float inv = 1.0f / (float)Nn;
    float mu  = stats[c] * inv;
    float var = stats[Cc + c] * inv - mu * mu;
    float sc  = __ldg(g + c) * rsqrtf(var + 1e-5f);
    scsh[c]      = sc;
    scsh[Cc + c] = fmaf(-mu, sc, __ldg(bt + c));
}

__global__ void apply_bn(const float* __restrict__ t2,
                         const float* __restrict__ scsh,
                         float* __restrict__ outp, int do_relu) {
    int idx = blockIdx.x * blockDim.x + threadIdx.x;
    if (idx >= Nn * 128) return;
    int c = idx & 127;
    float v = fmaf(scsh[c], t2[idx], scsh[128 + c]);
    outp[idx] = do_relu ? fmaxf(v, 0.f) : v;
}

// ======================= split-tf32 mma.sync GEMM =======================
// C = X @ W + bias (+ column stats), fp32-accurate via hi/lo 3-term MMA.
// MODE 0: X = (1+eps[layer])*A + A2      MODE 1: X = relu(sc[k]*A + sh[k])
template <int K, int NC, int MODE>
__global__ void __launch_bounds__(256) mma_gemm(
    const float* __restrict__ A, const float* __restrict__ A2,
    const float* __restrict__ epsp, int layer,
    const float* __restrict__ scsh,
    const uint32_t* __restrict__ Wt_hi, const uint32_t* __restrict__ Wt_lo,
    const float* __restrict__ bias,
    float* __restrict__ C, float* __restrict__ stats)
{
    extern __shared__ char dynsmem[];
    typedef float Tile[128][36];
    Tile& As_hi = *(Tile*)(dynsmem);
    Tile& As_lo = *(Tile*)(dynsmem + 18432);
    Tile& Bs_hi = *(Tile*)(dynsmem + 36864);
    Tile& Bs_lo = *(Tile*)(dynsmem + 55296);
    __shared__ float s_sum[128];
    __shared__ float s_sq[128];

    const int tid  = threadIdx.x;
    const int wid  = tid >> 5, lane = tid & 31;
    const int g    = lane >> 2, t4 = lane & 3;
    const int wm   = wid & 3;        // warp row tile (32 rows)
    const int wn   = wid >> 2;       // warp col tile (64 cols)
    const int rowBase = blockIdx.x * 128;
    const int colBase = blockIdx.y * 128;

    if (tid < 128) { s_sum[tid] = 0.f; s_sq[tid] = 0.f; }

    float alpha = 1.0f;
    if (MODE == 0) alpha = 1.0f + __ldg(epsp + layer);
    const float* shv = scsh + K;

    float c[2][8][4];
#pragma unroll
    for (int mt = 0; mt < 2; mt++)
#pragma unroll
        for (int nt = 0; nt < 8; nt++)
#pragma unroll
            for (int j = 0; j < 4; j++) c[mt][nt][j] = 0.f;

    const int lr = tid >> 1;               // 0..127
    const int lk = (tid & 1) * 16;         // 0 or 16

    for (int k0 = 0; k0 < K; k0 += 32) {
        // ---- A chunk: fused transform, hi/lo split ----
        {
            int rg = rowBase + lr;
            const float* Ap = A + (size_t)rg * K + k0 + lk;
#pragma unroll
            for (int q = 0; q < 4; q++) {
                float4 v = make_float4(0.f, 0.f, 0.f, 0.f);
                if (rg < Nn) {
                    float4 av = *(const float4*)(Ap + q * 4);
                    if (MODE == 0) {
                        const float4 gv = *(const float4*)(A2 + (size_t)rg * K + k0 + lk + q * 4);
                        v.x = fmaf(alpha, av.x, gv.x);
                        v.y = fmaf(alpha, av.y, gv.y);
                        v.z = fmaf(alpha, av.z, gv.z);
                        v.w = fmaf(alpha, av.w, gv.w);
                    } else {
                        int kg = k0 + lk + q * 4;
                        v.x = fmaxf(fmaf(__ldg(scsh + kg + 0), av.x, __ldg(shv + kg + 0)), 0.f);
                        v.y = fmaxf(fmaf(__ldg(scsh + kg + 1), av.y, __ldg(shv + kg + 1)), 0.f);
                        v.z = fmaxf(fmaf(__ldg(scsh + kg + 2), av.z, __ldg(shv + kg + 2)), 0.f);
                        v.w = fmaxf(fmaf(__ldg(scsh + kg + 3), av.w, __ldg(shv + kg + 3)), 0.f);
                    }
                }
                uint32_t hx = f2tf32(v.x), hy = f2tf32(v.y), hz = f2tf32(v.z), hw = f2tf32(v.w);
                float4 ho, lo;
                ho.x = __uint_as_float(hx); ho.y = __uint_as_float(hy);
                ho.z = __uint_as_float(hz); ho.w = __uint_as_float(hw);
                lo.x = __uint_as_float(f2tf32(v.x - ho.x));
                lo.y = __uint_as_float(f2tf32(v.y - ho.y));
                lo.z = __uint_as_float(f2tf32(v.z - ho.z));
                lo.w = __uint_as_float(f2tf32(v.w - ho.w));
                *(float4*)&As_hi[lr][lk + q * 4] = ho;
                *(float4*)&As_lo[lr][lk + q * 4] = lo;
            }
        }
        // ---- B chunk: straight copies of prebuilt hi/lo ----
        {
            int n = colBase + lr;
            const uint32_t* Wh = Wt_hi + (size_t)n * K + k0 + lk;
            const uint32_t* Wl = Wt_lo + (size_t)n * K + k0 + lk;
#pragma unroll
            for (int q = 0; q < 4; q++) {
                uint4 wh = *(const uint4*)(Wh + q * 4);
                uint4 wl = *(const uint4*)(Wl + q * 4);
                *(uint4*)&Bs_hi[lr][lk + q * 4] = wh;
                *(uint4*)&Bs_lo[lr][lk + q * 4] = wl;
            }
        }
        __syncthreads();

#pragma unroll
        for (int ks = 0; ks < 4; ks++) {
            const int kk = ks * 8;
            uint32_t ah[2][4], al[2][4];
#pragma unroll
            for (int mt = 0; mt < 2; mt++) {
                int r0 = wm * 32 + mt * 16 + g;
                ah[mt][0] = __float_as_uint(As_hi[r0][kk + t4]);
                ah[mt][1] = __float_as_uint(As_hi[r0 + 8][kk + t4]);
                ah[mt][2] = __float_as_uint(As_hi[r0][kk + t4 + 4]);
                ah[mt][3] = __float_as_uint(As_hi[r0 + 8][kk + t4 + 4]);
                al[mt][0] = __float_as_uint(As_lo[r0][kk + t4]);
                al[mt][1] = __float_as_uint(As_lo[r0 + 8][kk + t4]);
                al[mt][2] = __float_as_uint(As_lo[r0][kk + t4 + 4]);
                al[mt][3] = __float_as_uint(As_lo[r0 + 8][kk + t4 + 4]);
            }
#pragma unroll
            for (int nt = 0; nt < 8; nt++) {
                int n0 = wn * 64 + nt * 8 + g;
                uint32_t bh0 = __float_as_uint(Bs_hi[n0][kk + t4]);
                uint32_t bh1 = __float_as_uint(Bs_hi[n0][kk + t4 + 4]);
                uint32_t bl0 = __float_as_uint(Bs_lo[n0][kk + t4]);
                uint32_t bl1 = __float_as_uint(Bs_lo[n0][kk + t4 + 4]);
#pragma unroll
                for (int mt = 0; mt < 2; mt++) {
                    mma_tf32(c[mt][nt], al[mt], bh0, bh1);
                    mma_tf32(c[mt][nt], ah[mt], bl0, bl1);
                    mma_tf32(c[mt][nt], ah[mt], bh0, bh1);
                }
            }
        }
        __syncthreads();
    }

    // ---- epilogue: bias, store C, column stats ----
#pragma unroll
    for (int nt = 0; nt < 8; nt++) {
        int cl = wn * 64 + nt * 8 + t4 * 2;
        float b0 = __ldg(bias + colBase + cl);
        float b1 = __ldg(bias + colBase + cl + 1);
        float cs0 = 0.f, cq0 = 0.f, cs1 = 0.f, cq1 = 0.f;
#pragma unroll
        for (int mt = 0; mt < 2; mt++) {
            int r0 = rowBase + wm * 32 + mt * 16 + g;
#pragma unroll
            for (int half = 0; half < 2; half++) {
                int rg = r0 + half * 8;
                float v0 = c[mt][nt][half * 2] + b0;
                float v1 = c[mt][nt][half * 2 + 1] + b1;
                if (rg < Nn) {
                    *(float2*)(C + (size_t)rg * NC + colBase + cl) = make_float2(v0, v1);
                    cs0 += v0; cq0 += v0 * v0;
                    cs1 += v1; cq1 += v1 * v1;
                }
            }
        }
#pragma unroll
        for (int o = 4; o <= 16; o <<= 1) {
            cs0 += __shfl_xor_sync(0xFFFFFFFFu, cs0, o);
            cq0 += __shfl_xor_sync(0xFFFFFFFFu, cq0, o);
            cs1 += __shfl_xor_sync(0xFFFFFFFFu, cs1, o);
            cq1 += __shfl_xor_sync(0xFFFFFFFFu, cq1, o);
        }
        if (g == 0) {
            atomicAdd(&s_sum[cl], cs0);
            atomicAdd(&s_sq[cl], cq0);
            atomicAdd(&s_sum[cl + 1], cs1);
            atomicAdd(&s_sq[cl + 1], cq1);
        }
    }
    __syncthreads();
    if (tid < 128) {
        atomicAdd(&stats[colBase + tid],      s_sum[tid]);
        atomicAdd(&stats[NC + colBase + tid], s_sq[tid]);
    }
}

// ======================= launch =======================
extern "C" void kernel_launch(void* const* d_in, const int* in_sizes, int n_in,
                              void* d_out, int out_size) {
    const int*   x    = (const int*)d_in[0];
    const int*   ei   = (const int*)d_in[1];
    const int*   ea   = (const int*)d_in[2];
    const float* ew   = (const float*)d_in[3];
    const float* ae   = (const float*)d_in[4];
    const float* be   = (const float*)d_in[5];
    const float* eps  = (const float*)d_in[6];
    const float* W1   = (const float*)d_in[7];
    const float* b1   = (const float*)d_in[8];
    const float* g1   = (const float*)d_in[9];
    const float* bt1  = (const float*)d_in[10];
    const float* W2   = (const float*)d_in[11];
    const float* b2   = (const float*)d_in[12];
    const float* go   = (const float*)d_in[13];
    const float* bto  = (const float*)d_in[14];
    float* out = (float*)d_out;

    float *h, *agg, *t1, *t2, *st1, *st2, *sc1, *sc2;
    uint32_t *wt1h, *wt1l, *wt2h, *wt2l;
    cudaGetSymbolAddress((void**)&h,    g_h);
    cudaGetSymbolAddress((void**)&agg,  g_agg);
    cudaGetSymbolAddress((void**)&t1,   g_t1);
    cudaGetSymbolAddress((void**)&t2,   g_t2);
    cudaGetSymbolAddress((void**)&wt1h, g_wt1_hi);
    cudaGetSymbolAddress((void**)&wt1l, g_wt1_lo);
    cudaGetSymbolAddress((void**)&wt2h, g_wt2_hi);
    cudaGetSymbolAddress((void**)&wt2l, g_wt2_lo);
    cudaGetSymbolAddress((void**)&st1,  g_stats1);
    cudaGetSymbolAddress((void**)&st2,  g_stats2);
    cudaGetSymbolAddress((void**)&sc1,  g_sc1);
    cudaGetSymbolAddress((void**)&sc2,  g_sc2);

    const int DSMEM = 4 * 128 * 36 * 4;  // 73728
    static int attr_set = 0;
    cudaFuncSetAttribute(mma_gemm<128, 256, 0>,
                         cudaFuncAttributeMaxDynamicSharedMemorySize, DSMEM);
    cudaFuncSetAttribute(mma_gemm<256, 128, 1>,
                         cudaFuncAttributeMaxDynamicSharedMemorySize, DSMEM);
    (void)attr_set;

    const int elem_blocks = (Nn * 128 + 255) / 256;
    const int gemm_blocks = (Nn + 127) / 128;

    init_h_kernel<<<elem_blocks, 256>>>(x, ae, h);

    for (int l = 0; l < Ll; l++) {
        cudaMemsetAsync(agg, 0, (size_t)Nn * 128 * sizeof(float));
        cudaMemsetAsync(st1, 0, 512 * sizeof(float));
        cudaMemsetAsync(st2, 0, 256 * sizeof(float));

        transpose_w_kernel<<<128, 256>>>(W1 + (size_t)l * 128 * 256, wt1h, wt1l, 128, 256);
        transpose_w_kernel<<<128, 256>>>(W2 + (size_t)l * 256 * 128, wt2h, wt2l, 256, 128);

        edge_kernel<<<2048, 256>>>(h, be + (size_t)l * 3 * 8 * 128, ei, ea, ew, agg);

        dim3 grid1(gemm_blocks, 2);
        mma_gemm<128, 256, 0><<<grid1, 256, DSMEM>>>(
            h, agg, eps, l, sc1, wt1h, wt1l, b1 + l * 256, t1, st1);
        finalize_bn<<<1, 256>>>(st1, g1 + l * 256, bt1 + l * 256, sc1, 256);

        dim3 grid2(gemm_blocks, 1);
        mma_gemm<256, 128, 1><<<grid2, 256, DSMEM>>>(
            t1, (const float*)nullptr, (const float*)nullptr, 0, sc1,
            wt2h, wt2l, b2 + l * 128, t2, st2);
        finalize_bn<<<1, 128>>>(st2, go + l * 128, bto + l * 128, sc2, 128);

        float* dsth = (l == Ll - 1) ? out : h;
        apply_bn<<<elem_blocks, 256>>>(t2, sc2, dsth, (l < Ll - 1) ? 1 : 0);
    }
}

// round 7
// speedup vs baseline: 1.7084x; 1.0730x over previous
#include <cuda_runtime.h>
#include <cuda_bf16.h>
#include <cstdint>
#include <cstddef>

#define Nn 100000
#define Ee 500000
#define Ll 5

// -------- scratch (device globals: allocation-free) --------
__device__ __align__(16) float g_h[(size_t)Nn * 128];
__device__ __align__(16) float g_agg[(size_t)Nn * 128];
__device__ __align__(16) float g_t1[(size_t)Nn * 256];
__device__ __align__(16) float g_t2[(size_t)Nn * 128];
__device__ __align__(16) __nv_bfloat16 g_wt1_hi[256 * 128];
__device__ __align__(16) __nv_bfloat16 g_wt1_lo[256 * 128];
__device__ __align__(16) __nv_bfloat16 g_wt2_hi[128 * 256];
__device__ __align__(16) __nv_bfloat16 g_wt2_lo[128 * 256];
__device__ float g_stats1[512];
__device__ float g_stats2[256];
__device__ float g_sc1[512];
__device__ float g_sc2[256];

__device__ __forceinline__ void mma_bf16(float* c, const uint32_t* a, uint32_t b0, uint32_t b1) {
    asm volatile(
        "mma.sync.aligned.m16n8k16.row.col.f32.bf16.bf16.f32 "
        "{%0,%1,%2,%3}, {%4,%5,%6,%7}, {%8,%9}, {%0,%1,%2,%3};"
        : "+f"(c[0]), "+f"(c[1]), "+f"(c[2]), "+f"(c[3])
        : "r"(a[0]), "r"(a[1]), "r"(a[2]), "r"(a[3]), "r"(b0), "r"(b1));
}

// ======================= small kernels =======================
__global__ void init_h_kernel(const int* __restrict__ x,
                              const float* __restrict__ ae,
                              float* __restrict__ h) {
    int idx = blockIdx.x * blockDim.x + threadIdx.x;
    if (idx >= Nn * 128) return;
    int n = idx >> 7, d = idx & 127;
    float s = 0.f;
#pragma unroll
    for (int f = 0; f < 9; f++) {
        int xi = __ldg(x + n * 9 + f);
        s += __ldg(ae + (((size_t)(f * 120 + xi)) << 7) + d);
    }
    h[idx] = s;
}

__global__ void __launch_bounds__(256) edge_kernel(
    const float* __restrict__ h, const float* __restrict__ be,
    const int* __restrict__ ei, const int* __restrict__ ea,
    const float* __restrict__ ew, float* __restrict__ agg)
{
    __shared__ __align__(16) float sbe[3 * 8 * 128];
    for (int i = threadIdx.x; i < 3 * 8 * 128; i += 256) sbe[i] = be[i];
    __syncthreads();

    int gwarp = (blockIdx.x * 256 + threadIdx.x) >> 5;
    int lane  = threadIdx.x & 31;
    int nw    = (gridDim.x * 256) >> 5;
    int d0    = lane * 4;

    for (int e = gwarp; e < Ee; e += nw) {
        int src = __ldg(ei + e);
        int dst = __ldg(ei + Ee + e);
        int a0  = __ldg(ea + e * 3 + 0);
        int a1  = __ldg(ea + e * 3 + 1);
        int a2  = __ldg(ea + e * 3 + 2);
        float w = __ldg(ew + e);

        const float4 hv = *(const float4*)(h + (size_t)src * 128 + d0);
        const float4 e0 = *(const float4*)(sbe + (a0      ) * 128 + d0);
        const float4 e1 = *(const float4*)(sbe + (8  + a1 ) * 128 + d0);
        const float4 e2 = *(const float4*)(sbe + (16 + a2 ) * 128 + d0);

        float m0 = fmaxf(hv.x + e0.x + e1.x + e2.x, 0.f) * w;
        float m1 = fmaxf(hv.y + e0.y + e1.y + e2.y, 0.f) * w;
        float m2 = fmaxf(hv.z + e0.z + e1.z + e2.z, 0.f) * w;
        float m3 = fmaxf(hv.w + e0.w + e1.w + e2.w, 0.f) * w;

        float* p = agg + (size_t)dst * 128 + d0;
        asm volatile("red.global.add.v4.f32 [%0], {%1,%2,%3,%4};"
                     :: "l"(p), "f"(m0), "f"(m1), "f"(m2), "f"(m3) : "memory");
    }
}

// Wt_hi/lo[n*K + k] = bf16 hi/lo split of W[k*NC + n]
__global__ void transpose_w_kernel(const float* __restrict__ W,
                                   __nv_bfloat16* __restrict__ Wt_hi,
                                   __nv_bfloat16* __restrict__ Wt_lo, int K, int NC) {
    int idx = blockIdx.x * 256 + threadIdx.x;
    if (idx >= K * NC) return;
    int n = idx / K, k = idx - n * K;
    float w = __ldg(W + (size_t)k * NC + n);
    __nv_bfloat16 hi = __float2bfloat16(w);
    Wt_hi[idx] = hi;
    Wt_lo[idx] = __float2bfloat16(w - __bfloat162float(hi));
}

__global__ void finalize_bn(const float* __restrict__ stats,
                            const float* __restrict__ g,
                            const float* __restrict__ bt,
                            float* __restrict__ scsh, int Cc) {
    int c = blockIdx.x * blockDim.x + threadIdx.x;
    if (c >= Cc) return;
    const float inv = 1.0f / (float)Nn;
    float mu  = stats[c] * inv;
    float var = stats[Cc + c] * inv - mu * mu;
    float sc  = __ldg(g + c) * rsqrtf(var + 1e-5f);
    scsh[c]      = sc;
    scsh[Cc + c] = fmaf(-mu, sc, __ldg(bt + c));
}

__global__ void apply_bn(const float* __restrict__ t2,
                         const float* __restrict__ scsh,
                         float* __restrict__ outp, int do_relu) {
    int idx = blockIdx.x * blockDim.x + threadIdx.x;
    if (idx >= Nn * 128) return;
    int c = idx & 127;
    float v = fmaf(scsh[c], t2[idx], scsh[128 + c]);
    outp[idx] = do_relu ? fmaxf(v, 0.f) : v;
}

// ======================= bf16 hi/lo mma.sync GEMM =======================
// C = X @ W + bias (+ column stats). fp32-near via 3-term bf16 split:
//   x = hi + lo (bf16 each);  x*w ~= xh*wh + xh*wl + xl*wh
// MODE 0: X = (1+eps[layer])*A + A2      MODE 1: X = relu(sc[k]*A + sh[k])
template <int K, int NC, int MODE>
__global__ void __launch_bounds__(256) mma_gemm(
    const float* __restrict__ A, const float* __restrict__ A2,
    const float* __restrict__ epsp, int layer,
    const float* __restrict__ scsh,
    const __nv_bfloat16* __restrict__ Wt_hi, const __nv_bfloat16* __restrict__ Wt_lo,
    const float* __restrict__ bias,
    float* __restrict__ C, float* __restrict__ stats)
{
    // 32 bf16 per row-chunk = 16 dwords, padded to 20 dwords (conflict-free)
    __shared__ uint32_t As_hi[128][20];
    __shared__ uint32_t As_lo[128][20];
    __shared__ uint32_t Bs_hi[128][20];
    __shared__ uint32_t Bs_lo[128][20];
    __shared__ float s_sum[128];
    __shared__ float s_sq[128];

    const int tid  = threadIdx.x;
    const int wid  = tid >> 5, lane = tid & 31;
    const int g    = lane >> 2, t4 = lane & 3;
    const int wm   = wid & 3;        // warp row tile (32 rows)
    const int wn   = wid >> 2;       // warp col tile (64 cols)
    const int rowBase = blockIdx.x * 128;
    const int colBase = blockIdx.y * 128;

    if (tid < 128) { s_sum[tid] = 0.f; s_sq[tid] = 0.f; }

    float alpha = 1.0f;
    if (MODE == 0) alpha = 1.0f + __ldg(epsp + layer);
    const float* shv = scsh + K;

    float c[2][8][4];
#pragma unroll
    for (int mt = 0; mt < 2; mt++)
#pragma unroll
        for (int nt = 0; nt < 8; nt++)
#pragma unroll
            for (int j = 0; j < 4; j++) c[mt][nt][j] = 0.f;

    const int lr    = tid >> 1;            // 0..127 row for loading
    const int lk    = (tid & 1) * 16;      // 0 or 16 (element offset in chunk)
    const int lk_dw = (tid & 1) * 8;       // dword offset in smem row

    for (int k0 = 0; k0 < K; k0 += 32) {
        // ---- A chunk: fused transform, bf16 hi/lo split ----
        {
            int rg = rowBase + lr;
            const float* Ap = A + (size_t)rg * K + k0 + lk;
            uint32_t hi_d[8], lo_d[8];
#pragma unroll
            for (int q = 0; q < 4; q++) {
                float4 v = make_float4(0.f, 0.f, 0.f, 0.f);
                if (rg < Nn) {
                    float4 av = *(const float4*)(Ap + q * 4);
                    if (MODE == 0) {
                        const float4 gv = *(const float4*)(A2 + (size_t)rg * K + k0 + lk + q * 4);
                        v.x = fmaf(alpha, av.x, gv.x);
                        v.y = fmaf(alpha, av.y, gv.y);
                        v.z = fmaf(alpha, av.z, gv.z);
                        v.w = fmaf(alpha, av.w, gv.w);
                    } else {
                        int kg = k0 + lk + q * 4;
                        v.x = fmaxf(fmaf(__ldg(scsh + kg + 0), av.x, __ldg(shv + kg + 0)), 0.f);
                        v.y = fmaxf(fmaf(__ldg(scsh + kg + 1), av.y, __ldg(shv + kg + 1)), 0.f);
                        v.z = fmaxf(fmaf(__ldg(scsh + kg + 2), av.z, __ldg(shv + kg + 2)), 0.f);
                        v.w = fmaxf(fmaf(__ldg(scsh + kg + 3), av.w, __ldg(shv + kg + 3)), 0.f);
                    }
                }
                __nv_bfloat162 h0 = __floats2bfloat162_rn(v.x, v.y);   // .x low half
                __nv_bfloat162 h1 = __floats2bfloat162_rn(v.z, v.w);
                float rx = v.x - __bfloat162float(h0.x);
                float ry = v.y - __bfloat162float(h0.y);
                float rz = v.z - __bfloat162float(h1.x);
                float rw = v.w - __bfloat162float(h1.y);
                __nv_bfloat162 l0 = __floats2bfloat162_rn(rx, ry);
                __nv_bfloat162 l1 = __floats2bfloat162_rn(rz, rw);
                hi_d[q * 2 + 0] = *(uint32_t*)&h0;
                hi_d[q * 2 + 1] = *(uint32_t*)&h1;
                lo_d[q * 2 + 0] = *(uint32_t*)&l0;
                lo_d[q * 2 + 1] = *(uint32_t*)&l1;
            }
            *(uint4*)&As_hi[lr][lk_dw]     = make_uint4(hi_d[0], hi_d[1], hi_d[2], hi_d[3]);
            *(uint4*)&As_hi[lr][lk_dw + 4] = make_uint4(hi_d[4], hi_d[5], hi_d[6], hi_d[7]);
            *(uint4*)&As_lo[lr][lk_dw]     = make_uint4(lo_d[0], lo_d[1], lo_d[2], lo_d[3]);
            *(uint4*)&As_lo[lr][lk_dw + 4] = make_uint4(lo_d[4], lo_d[5], lo_d[6], lo_d[7]);
        }
        // ---- B chunk: straight copies of prebuilt bf16 hi/lo ----
        {
            int n = colBase + lr;
            const __nv_bfloat16* Wh = Wt_hi + (size_t)n * K + k0 + lk;
            const __nv_bfloat16* Wl = Wt_lo + (size_t)n * K + k0 + lk;
            uint4 wh0 = *(const uint4*)(Wh);      // 8 halves
            uint4 wh1 = *(const uint4*)(Wh + 8);
            uint4 wl0 = *(const uint4*)(Wl);
            uint4 wl1 = *(const uint4*)(Wl + 8);
            *(uint4*)&Bs_hi[lr][lk_dw]     = wh0;
            *(uint4*)&Bs_hi[lr][lk_dw + 4] = wh1;
            *(uint4*)&Bs_lo[lr][lk_dw]     = wl0;
            *(uint4*)&Bs_lo[lr][lk_dw + 4] = wl1;
        }
        __syncthreads();

#pragma unroll
        for (int ks = 0; ks < 2; ks++) {
            const int kd = ks * 8;         // dword offset of k16 step
            uint32_t ah[2][4], al[2][4];
#pragma unroll
            for (int mt = 0; mt < 2; mt++) {
                int r0 = wm * 32 + mt * 16 + g;
                ah[mt][0] = As_hi[r0][kd + t4];
                ah[mt][1] = As_hi[r0 + 8][kd + t4];
                ah[mt][2] = As_hi[r0][kd + 4 + t4];
                ah[mt][3] = As_hi[r0 + 8][kd + 4 + t4];
                al[mt][0] = As_lo[r0][kd + t4];
                al[mt][1] = As_lo[r0 + 8][kd + t4];
                al[mt][2] = As_lo[r0][kd + 4 + t4];
                al[mt][3] = As_lo[r0 + 8][kd + 4 + t4];
            }
#pragma unroll
            for (int nt = 0; nt < 8; nt++) {
                int n0 = wn * 64 + nt * 8 + g;
                uint32_t bh0 = Bs_hi[n0][kd + t4];
                uint32_t bh1 = Bs_hi[n0][kd + 4 + t4];
                uint32_t bl0 = Bs_lo[n0][kd + t4];
                uint32_t bl1 = Bs_lo[n0][kd + 4 + t4];
#pragma unroll
                for (int mt = 0; mt < 2; mt++) {
                    mma_bf16(c[mt][nt], al[mt], bh0, bh1);
                    mma_bf16(c[mt][nt], ah[mt], bl0, bl1);
                    mma_bf16(c[mt][nt], ah[mt], bh0, bh1);
                }
            }
        }
        __syncthreads();
    }

    // ---- epilogue: bias, store C, column stats ----
#pragma unroll
    for (int nt = 0; nt < 8; nt++) {
        int cl = wn * 64 + nt * 8 + t4 * 2;
        float b0 = __ldg(bias + colBase + cl);
        float b1 = __ldg(bias + colBase + cl + 1);
        float cs0 = 0.f, cq0 = 0.f, cs1 = 0.f, cq1 = 0.f;
#pragma unroll
        for (int mt = 0; mt < 2; mt++) {
            int r0 = rowBase + wm * 32 + mt * 16 + g;
#pragma unroll
            for (int half = 0; half < 2; half++) {
                int rg = r0 + half * 8;
                float v0 = c[mt][nt][half * 2] + b0;
                float v1 = c[mt][nt][half * 2 + 1] + b1;
                if (rg < Nn) {
                    *(float2*)(C + (size_t)rg * NC + colBase + cl) = make_float2(v0, v1);
                    cs0 += v0; cq0 += v0 * v0;
                    cs1 += v1; cq1 += v1 * v1;
                }
            }
        }
#pragma unroll
        for (int o = 4; o <= 16; o <<= 1) {
            cs0 += __shfl_xor_sync(0xFFFFFFFFu, cs0, o);
            cq0 += __shfl_xor_sync(0xFFFFFFFFu, cq0, o);
            cs1 += __shfl_xor_sync(0xFFFFFFFFu, cs1, o);
            cq1 += __shfl_xor_sync(0xFFFFFFFFu, cq1, o);
        }
        if (g == 0) {
            atomicAdd(&s_sum[cl], cs0);
            atomicAdd(&s_sq[cl], cq0);
            atomicAdd(&s_sum[cl + 1], cs1);
            atomicAdd(&s_sq[cl + 1], cq1);
        }
    }
    __syncthreads();
    if (tid < 128) {
        atomicAdd(&stats[colBase + tid],      s_sum[tid]);
        atomicAdd(&stats[NC + colBase + tid], s_sq[tid]);
    }
}

// ======================= launch =======================
extern "C" void kernel_launch(void* const* d_in, const int* in_sizes, int n_in,
                              void* d_out, int out_size) {
    const int*   x    = (const int*)d_in[0];
    const int*   ei   = (const int*)d_in[1];
    const int*   ea   = (const int*)d_in[2];
    const float* ew   = (const float*)d_in[3];
    const float* ae   = (const float*)d_in[4];
    const float* be   = (const float*)d_in[5];
    const float* eps  = (const float*)d_in[6];
    const float* W1   = (const float*)d_in[7];
    const float* b1   = (const float*)d_in[8];
    const float* g1   = (const float*)d_in[9];
    const float* bt1  = (const float*)d_in[10];
    const float* W2   = (const float*)d_in[11];
    const float* b2   = (const float*)d_in[12];
    const float* go   = (const float*)d_in[13];
    const float* bto  = (const float*)d_in[14];
    float* out = (float*)d_out;

    float *h, *agg, *t1, *t2, *st1, *st2, *sc1, *sc2;
    __nv_bfloat16 *wt1h, *wt1l, *wt2h, *wt2l;
    cudaGetSymbolAddress((void**)&h,    g_h);
    cudaGetSymbolAddress((void**)&agg,  g_agg);
    cudaGetSymbolAddress((void**)&t1,   g_t1);
    cudaGetSymbolAddress((void**)&t2,   g_t2);
    cudaGetSymbolAddress((void**)&wt1h, g_wt1_hi);
    cudaGetSymbolAddress((void**)&wt1l, g_wt1_lo);
    cudaGetSymbolAddress((void**)&wt2h, g_wt2_hi);
    cudaGetSymbolAddress((void**)&wt2l, g_wt2_lo);
    cudaGetSymbolAddress((void**)&st1,  g_stats1);
    cudaGetSymbolAddress((void**)&st2,  g_stats2);
    cudaGetSymbolAddress((void**)&sc1,  g_sc1);
    cudaGetSymbolAddress((void**)&sc2,  g_sc2);

    const int elem_blocks = (Nn * 128 + 255) / 256;
    const int gemm_blocks = (Nn + 127) / 128;

    init_h_kernel<<<elem_blocks, 256>>>(x, ae, h);

    for (int l = 0; l < Ll; l++) {
        cudaMemsetAsync(agg, 0, (size_t)Nn * 128 * sizeof(float));
        cudaMemsetAsync(st1, 0, 512 * sizeof(float));
        cudaMemsetAsync(st2, 0, 256 * sizeof(float));

        transpose_w_kernel<<<128, 256>>>(W1 + (size_t)l * 128 * 256, wt1h, wt1l, 128, 256);
        transpose_w_kernel<<<128, 256>>>(W2 + (size_t)l * 256 * 128, wt2h, wt2l, 256, 128);

        edge_kernel<<<2048, 256>>>(h, be + (size_t)l * 3 * 8 * 128, ei, ea, ew, agg);

        dim3 grid1(gemm_blocks, 2);
        mma_gemm<128, 256, 0><<<grid1, 256>>>(
            h, agg, eps, l, sc1, wt1h, wt1l, b1 + l * 256, t1, st1);
        finalize_bn<<<1, 256>>>(st1, g1 + l * 256, bt1 + l * 256, sc1, 256);

        dim3 grid2(gemm_blocks, 1);
        mma_gemm<256, 128, 1><<<grid2, 256>>>(
            t1, (const float*)nullptr, (const float*)nullptr, 0, sc1,
            wt2h, wt2l, b2 + l * 128, t2, st2);
        finalize_bn<<<1, 128>>>(st2, go + l * 128, bto + l * 128, sc2, 128);

        float* dsth = (l == Ll - 1) ? out : h;
        apply_bn<<<elem_blocks, 256>>>(t2, sc2, dsth, (l < Ll - 1) ? 1 : 0);
    }
}

// round 8
// speedup vs baseline: 1.8435x; 1.0791x over previous
#include <cuda_runtime.h>
#include <cuda_bf16.h>
#include <cstdint>
#include <cstddef>

#define Nn 100000
#define Ee 500000
#define Ll 5

// -------- scratch (device globals: allocation-free) --------
__device__ __align__(16) float g_h[(size_t)Nn * 128];
__device__ __align__(16) float g_agg[(size_t)Nn * 128];
__device__ __align__(16) float g_t1[(size_t)Nn * 256];
__device__ __align__(16) float g_t2[(size_t)Nn * 128];
__device__ __align__(16) __nv_bfloat16 g_wt1_hi[256 * 128];
__device__ __align__(16) __nv_bfloat16 g_wt1_lo[256 * 128];
__device__ __align__(16) __nv_bfloat16 g_wt2_hi[128 * 256];
__device__ __align__(16) __nv_bfloat16 g_wt2_lo[128 * 256];
__device__ float g_stats[768];   // [0:512) gemm1 sums/sumsq, [512:768) gemm2
__device__ float g_sc1[512];
__device__ float g_sc2[256];

// ======================= PTX helpers =======================
__device__ __forceinline__ void mma_bf16(float* c, const uint32_t* a, uint32_t b0, uint32_t b1) {
    asm volatile(
        "mma.sync.aligned.m16n8k16.row.col.f32.bf16.bf16.f32 "
        "{%0,%1,%2,%3}, {%4,%5,%6,%7}, {%8,%9}, {%0,%1,%2,%3};"
        : "+f"(c[0]), "+f"(c[1]), "+f"(c[2]), "+f"(c[3])
        : "r"(a[0]), "r"(a[1]), "r"(a[2]), "r"(a[3]), "r"(b0), "r"(b1));
}
__device__ __forceinline__ void ldsm4(uint32_t addr, uint32_t* r) {
    asm volatile("ldmatrix.sync.aligned.m8n8.x4.shared.b16 {%0,%1,%2,%3}, [%4];"
                 : "=r"(r[0]), "=r"(r[1]), "=r"(r[2]), "=r"(r[3]) : "r"(addr));
}
#define CP_ASYNC16(dst, src) \
    asm volatile("cp.async.cg.shared.global [%0], [%1], 16;" :: "r"(dst), "l"(src))
#define CP_COMMIT() asm volatile("cp.async.commit_group;" ::: "memory")
#define CP_WAIT0()  asm volatile("cp.async.wait_group 0;" ::: "memory")

// ======================= small kernels =======================
__global__ void init_h_kernel(const int* __restrict__ x,
                              const float* __restrict__ ae,
                              float* __restrict__ h) {
    int idx = blockIdx.x * blockDim.x + threadIdx.x;
    if (idx >= Nn * 128) return;
    int n = idx >> 7, d = idx & 127;
    float s = 0.f;
#pragma unroll
    for (int f = 0; f < 9; f++) {
        int xi = __ldg(x + n * 9 + f);
        s += __ldg(ae + (((size_t)(f * 120 + xi)) << 7) + d);
    }
    h[idx] = s;
}

__global__ void zero_kernel(float* __restrict__ agg, float* __restrict__ stats) {
    int idx = blockIdx.x * blockDim.x + threadIdx.x;
    if (idx < 768) stats[idx] = 0.f;
    if (idx < Nn * 128) agg[idx] = 0.f;
}

__global__ void __launch_bounds__(256) edge_kernel(
    const float* __restrict__ h, const float* __restrict__ be,
    const int* __restrict__ ei, const int* __restrict__ ea,
    const float* __restrict__ ew, float* __restrict__ agg)
{
    __shared__ __align__(16) float sbe[3 * 8 * 128];
    for (int i = threadIdx.x; i < 3 * 8 * 128; i += 256) sbe[i] = be[i];
    __syncthreads();

    int gwarp = (blockIdx.x * 256 + threadIdx.x) >> 5;
    int lane  = threadIdx.x & 31;
    int nw    = (gridDim.x * 256) >> 5;
    int d0    = lane * 4;

    for (int e = gwarp; e < Ee; e += nw) {
        int src = __ldg(ei + e);
        int dst = __ldg(ei + Ee + e);
        int a0  = __ldg(ea + e * 3 + 0);
        int a1  = __ldg(ea + e * 3 + 1);
        int a2  = __ldg(ea + e * 3 + 2);
        float w = __ldg(ew + e);

        const float4 hv = *(const float4*)(h + (size_t)src * 128 + d0);
        const float4 e0 = *(const float4*)(sbe + (a0      ) * 128 + d0);
        const float4 e1 = *(const float4*)(sbe + (8  + a1 ) * 128 + d0);
        const float4 e2 = *(const float4*)(sbe + (16 + a2 ) * 128 + d0);

        float m0 = fmaxf(hv.x + e0.x + e1.x + e2.x, 0.f) * w;
        float m1 = fmaxf(hv.y + e0.y + e1.y + e2.y, 0.f) * w;
        float m2 = fmaxf(hv.z + e0.z + e1.z + e2.z, 0.f) * w;
        float m3 = fmaxf(hv.w + e0.w + e1.w + e2.w, 0.f) * w;

        float* p = agg + (size_t)dst * 128 + d0;
        asm volatile("red.global.add.v4.f32 [%0], {%1,%2,%3,%4};"
                     :: "l"(p), "f"(m0), "f"(m1), "f"(m2), "f"(m3) : "memory");
    }
}

// Wt_hi/lo[n*K + k] = bf16 hi/lo split of W[k*NC + n]
__global__ void transpose_w_kernel(const float* __restrict__ W,
                                   __nv_bfloat16* __restrict__ Wt_hi,
                                   __nv_bfloat16* __restrict__ Wt_lo, int K, int NC) {
    int idx = blockIdx.x * 256 + threadIdx.x;
    if (idx >= K * NC) return;
    int n = idx / K, k = idx - n * K;
    float w = __ldg(W + (size_t)k * NC + n);
    __nv_bfloat16 hi = __float2bfloat16(w);
    Wt_hi[idx] = hi;
    Wt_lo[idx] = __float2bfloat16(w - __bfloat162float(hi));
}

__global__ void finalize_bn(float* __restrict__ stats,
                            const float* __restrict__ g,
                            const float* __restrict__ bt,
                            float* __restrict__ scsh, int Cc) {
    int c = blockIdx.x * blockDim.x + threadIdx.x;
    if (c >= Cc) return;
    const float inv = 1.0f / (float)Nn;
    float mu  = stats[c] * inv;
    float var = stats[Cc + c] * inv - mu * mu;
    float sc  = __ldg(g + c) * rsqrtf(var + 1e-5f);
    scsh[c]      = sc;
    scsh[Cc + c] = fmaf(-mu, sc, __ldg(bt + c));
    stats[c] = 0.f;        // re-zero for next use (replay-safe: zero_kernel
    stats[Cc + c] = 0.f;   // zeroes at start of every launch sequence)
}

__global__ void apply_bn(const float* __restrict__ t2,
                         const float* __restrict__ scsh,
                         float* __restrict__ outp, int do_relu,
                         float* __restrict__ aggz) {
    int idx = blockIdx.x * blockDim.x + threadIdx.x;
    if (idx >= Nn * 128) return;
    int c = idx & 127;
    float v = fmaf(scsh[c], t2[idx], scsh[128 + c]);
    outp[idx] = do_relu ? fmaxf(v, 0.f) : v;
    if (aggz) aggz[idx] = 0.f;   // prep agg for next layer's edge scatter
}

// ======================= pipelined bf16 hi/lo mma GEMM =======================
// C = X @ W + bias (+ column stats). 3-term bf16 split for fp32-near accuracy.
// MODE 0: X = (1+eps[layer])*A + A2      MODE 1: X = relu(sc[k]*A + sh[k])
// Double-buffered k-chunks (32): cp.async for B, register prefetch for A,
// ldmatrix fragment loads, one __syncthreads per chunk.
template <int K, int NC, int MODE>
__global__ void __launch_bounds__(256, 1) mma_gemm(
    const float* __restrict__ A, const float* __restrict__ A2,
    const float* __restrict__ epsp, int layer,
    const float* __restrict__ scsh,
    const __nv_bfloat16* __restrict__ Wt_hi, const __nv_bfloat16* __restrict__ Wt_lo,
    const float* __restrict__ bias,
    float* __restrict__ C, float* __restrict__ stats)
{
    constexpr int CHUNKS = K / 32;
    constexpr int STG = 40960;                 // bytes per stage
    constexpr int AH = 0, AL = 10240, BH = 20480, BL = 30720;  // in-stage offsets
    // row stride 80 bytes (32 bf16 = 64B data + 16B pad, conflict-free)

    extern __shared__ char dsm[];
    __shared__ float s_sum[128];
    __shared__ float s_sq[128];

    uint32_t sb;
    asm("{ .reg .u64 t; cvta.to.shared.u64 t, %1; cvt.u32.u64 %0, t; }" : "=r"(sb) : "l"(dsm));

    const int tid  = threadIdx.x;
    const int wid  = tid >> 5, lane = tid & 31;
    const int g    = lane >> 2, t4 = lane & 3;
    const int wm   = wid & 3;
    const int wn   = wid >> 2;
    const int rowBase = blockIdx.x * 128;
    const int colBase = blockIdx.y * 128;

    if (tid < 128) { s_sum[tid] = 0.f; s_sq[tid] = 0.f; }

    float alpha = 1.0f;
    if (MODE == 0) alpha = 1.0f + __ldg(epsp + layer);
    const float* shv = scsh + K;

    // loader indices: each thread owns half a row (32B) of each tile
    const int lr  = tid >> 1;
    const int lk  = (tid & 1) * 16;      // element offset
    const int lkb = (tid & 1) * 32;      // byte offset

    // ldmatrix per-lane address offsets (byte, within array)
    const int aoff = (wm * 32 + ((lane >> 3) & 1) * 8 + (lane & 7)) * 80 + (lane >> 4) * 16;
    const int boff = (wn * 64 + (lane >> 4) * 8 + (lane & 7)) * 80 + ((lane >> 3) & 1) * 16;

    float acc[2][8][4];
#pragma unroll
    for (int mt = 0; mt < 2; mt++)
#pragma unroll
        for (int nt = 0; nt < 8; nt++)
#pragma unroll
            for (int j = 0; j < 4; j++) acc[mt][nt][j] = 0.f;

    const int rg = rowBase + lr;
    const bool rv = rg < Nn;

    // ---- helpers ----
    float4 pre[4];
    auto loadA = [&](int c) {
        const float* Ap = A + (size_t)rg * K + c * 32 + lk;
#pragma unroll
        for (int q = 0; q < 4; q++) {
            float4 v = make_float4(0.f, 0.f, 0.f, 0.f);
            if (rv) {
                float4 av = *(const float4*)(Ap + q * 4);
                if (MODE == 0) {
                    const float4 gv = *(const float4*)(A2 + (size_t)rg * K + c * 32 + lk + q * 4);
                    v.x = fmaf(alpha, av.x, gv.x);
                    v.y = fmaf(alpha, av.y, gv.y);
                    v.z = fmaf(alpha, av.z, gv.z);
                    v.w = fmaf(alpha, av.w, gv.w);
                } else {
                    int kg = c * 32 + lk + q * 4;
                    v.x = fmaxf(fmaf(__ldg(scsh + kg + 0), av.x, __ldg(shv + kg + 0)), 0.f);
                    v.y = fmaxf(fmaf(__ldg(scsh + kg + 1), av.y, __ldg(shv + kg + 1)), 0.f);
                    v.z = fmaxf(fmaf(__ldg(scsh + kg + 2), av.z, __ldg(shv + kg + 2)), 0.f);
                    v.w = fmaxf(fmaf(__ldg(scsh + kg + 3), av.w, __ldg(shv + kg + 3)), 0.f);
                }
            }
            pre[q] = v;
        }
    };
    auto cpasyncB = [&](int c, int stage) {
        const int n = colBase + lr;
        const __nv_bfloat16* Wh = Wt_hi + (size_t)n * K + c * 32 + lk;
        const __nv_bfloat16* Wl = Wt_lo + (size_t)n * K + c * 32 + lk;
        uint32_t dh = sb + stage * STG + BH + lr * 80 + lkb;
        uint32_t dl = sb + stage * STG + BL + lr * 80 + lkb;
        CP_ASYNC16(dh, Wh);
        CP_ASYNC16(dh + 16, Wh + 8);
        CP_ASYNC16(dl, Wl);
        CP_ASYNC16(dl + 16, Wl + 8);
    };
    auto storeA = [&](int stage) {
        uint32_t hi_d[8], lo_d[8];
#pragma unroll
        for (int q = 0; q < 4; q++) {
            float4 v = pre[q];
            __nv_bfloat162 h0 = __floats2bfloat162_rn(v.x, v.y);
            __nv_bfloat162 h1 = __floats2bfloat162_rn(v.z, v.w);
            float rx = v.x - __bfloat162float(h0.x);
            float ry = v.y - __bfloat162float(h0.y);
            float rz = v.z - __bfloat162float(h1.x);
            float rw = v.w - __bfloat162float(h1.y);
            __nv_bfloat162 l0 = __floats2bfloat162_rn(rx, ry);
            __nv_bfloat162 l1 = __floats2bfloat162_rn(rz, rw);
            hi_d[q * 2 + 0] = *(uint32_t*)&h0;
            hi_d[q * 2 + 1] = *(uint32_t*)&h1;
            lo_d[q * 2 + 0] = *(uint32_t*)&l0;
            lo_d[q * 2 + 1] = *(uint32_t*)&l1;
        }
        char* ah = dsm + stage * STG + AH + lr * 80 + lkb;
        char* al = dsm + stage * STG + AL + lr * 80 + lkb;
        *(uint4*)(ah)      = make_uint4(hi_d[0], hi_d[1], hi_d[2], hi_d[3]);
        *(uint4*)(ah + 16) = make_uint4(hi_d[4], hi_d[5], hi_d[6], hi_d[7]);
        *(uint4*)(al)      = make_uint4(lo_d[0], lo_d[1], lo_d[2], lo_d[3]);
        *(uint4*)(al + 16) = make_uint4(lo_d[4], lo_d[5], lo_d[6], lo_d[7]);
    };

    // ---- prologue: fill stage 0 with chunk 0 ----
    loadA(0);
    cpasyncB(0, 0);
    CP_COMMIT();
    storeA(0);
    CP_WAIT0();
    __syncthreads();

    // ---- main loop ----
    for (int c = 0; c < CHUNKS; c++) {
        const int cur = c & 1, nxt = (c + 1) & 1;
        const bool more = (c + 1) < CHUNKS;
        if (more) {
            loadA(c + 1);
            cpasyncB(c + 1, nxt);
            CP_COMMIT();
        }

        const uint32_t base = sb + cur * STG;
#pragma unroll
        for (int ks = 0; ks < 2; ks++) {
            const int kb = ks * 32;
            uint32_t ah[2][4], al2[2][4];
#pragma unroll
            for (int mt = 0; mt < 2; mt++) {
                ldsm4(base + AH + aoff + mt * 1280 + kb, ah[mt]);
                ldsm4(base + AL + aoff + mt * 1280 + kb, al2[mt]);
            }
#pragma unroll
            for (int p = 0; p < 4; p++) {
                uint32_t bh[4], bl[4];
                ldsm4(base + BH + boff + p * 1280 + kb, bh);
                ldsm4(base + BL + boff + p * 1280 + kb, bl);
#pragma unroll
                for (int mt = 0; mt < 2; mt++) {
                    mma_bf16(acc[mt][2 * p],     al2[mt], bh[0], bh[1]);
                    mma_bf16(acc[mt][2 * p],     ah[mt],  bl[0], bl[1]);
                    mma_bf16(acc[mt][2 * p],     ah[mt],  bh[0], bh[1]);
                    mma_bf16(acc[mt][2 * p + 1], al2[mt], bh[2], bh[3]);
                    mma_bf16(acc[mt][2 * p + 1], ah[mt],  bl[2], bl[3]);
                    mma_bf16(acc[mt][2 * p + 1], ah[mt],  bh[2], bh[3]);
                }
            }
        }

        if (more) storeA(nxt);
        CP_WAIT0();
        __syncthreads();
    }

    // ---- epilogue: bias, store C, column stats ----
#pragma unroll
    for (int nt = 0; nt < 8; nt++) {
        int cl = wn * 64 + nt * 8 + t4 * 2;
        float b0 = __ldg(bias + colBase + cl);
        float b1 = __ldg(bias + colBase + cl + 1);
        float cs0 = 0.f, cq0 = 0.f, cs1 = 0.f, cq1 = 0.f;
#pragma unroll
        for (int mt = 0; mt < 2; mt++) {
            int r0 = rowBase + wm * 32 + mt * 16 + g;
#pragma unroll
            for (int half = 0; half < 2; half++) {
                int rr = r0 + half * 8;
                float v0 = acc[mt][nt][half * 2] + b0;
                float v1 = acc[mt][nt][half * 2 + 1] + b1;
                if (rr < Nn) {
                    *(float2*)(C + (size_t)rr * NC + colBase + cl) = make_float2(v0, v1);
                    cs0 += v0; cq0 += v0 * v0;
                    cs1 += v1; cq1 += v1 * v1;
                }
            }
        }
#pragma unroll
        for (int o = 4; o <= 16; o <<= 1) {
            cs0 += __shfl_xor_sync(0xFFFFFFFFu, cs0, o);
            cq0 += __shfl_xor_sync(0xFFFFFFFFu, cq0, o);
            cs1 += __shfl_xor_sync(0xFFFFFFFFu, cs1, o);
            cq1 += __shfl_xor_sync(0xFFFFFFFFu, cq1, o);
        }
        if (g == 0) {
            atomicAdd(&s_sum[cl], cs0);
            atomicAdd(&s_sq[cl], cq0);
            atomicAdd(&s_sum[cl + 1], cs1);
            atomicAdd(&s_sq[cl + 1], cq1);
        }
    }
    __syncthreads();
    if (tid < 128) {
        atomicAdd(&stats[colBase + tid],      s_sum[tid]);
        atomicAdd(&stats[NC + colBase + tid], s_sq[tid]);
    }
}

// ======================= launch =======================
extern "C" void kernel_launch(void* const* d_in, const int* in_sizes, int n_in,
                              void* d_out, int out_size) {
    const int*   x    = (const int*)d_in[0];
    const int*   ei   = (const int*)d_in[1];
    const int*   ea   = (const int*)d_in[2];
    const float* ew   = (const float*)d_in[3];
    const float* ae   = (const float*)d_in[4];
    const float* be   = (const float*)d_in[5];
    const float* eps  = (const float*)d_in[6];
    const float* W1   = (const float*)d_in[7];
    const float* b1   = (const float*)d_in[8];
    const float* g1   = (const float*)d_in[9];
    const float* bt1  = (const float*)d_in[10];
    const float* W2   = (const float*)d_in[11];
    const float* b2   = (const float*)d_in[12];
    const float* go   = (const float*)d_in[13];
    const float* bto  = (const float*)d_in[14];
    float* out = (float*)d_out;

    float *h, *agg, *t1, *t2, *stats, *sc1, *sc2;
    __nv_bfloat16 *wt1h, *wt1l, *wt2h, *wt2l;
    cudaGetSymbolAddress((void**)&h,     g_h);
    cudaGetSymbolAddress((void**)&agg,   g_agg);
    cudaGetSymbolAddress((void**)&t1,    g_t1);
    cudaGetSymbolAddress((void**)&t2,    g_t2);
    cudaGetSymbolAddress((void**)&wt1h,  g_wt1_hi);
    cudaGetSymbolAddress((void**)&wt1l,  g_wt1_lo);
    cudaGetSymbolAddress((void**)&wt2h,  g_wt2_hi);
    cudaGetSymbolAddress((void**)&wt2l,  g_wt2_lo);
    cudaGetSymbolAddress((void**)&stats, g_stats);
    cudaGetSymbolAddress((void**)&sc1,   g_sc1);
    cudaGetSymbolAddress((void**)&sc2,   g_sc2);
    float* st1 = stats;         // 512 floats
    float* st2 = stats + 512;   // 256 floats

    const int DSMEM = 2 * 40960;  // 81920
    cudaFuncSetAttribute(mma_gemm<128, 256, 0>,
                         cudaFuncAttributeMaxDynamicSharedMemorySize, DSMEM);
    cudaFuncSetAttribute(mma_gemm<256, 128, 1>,
                         cudaFuncAttributeMaxDynamicSharedMemorySize, DSMEM);

    const int elem_blocks = (Nn * 128 + 255) / 256;
    const int gemm_blocks = (Nn + 127) / 128;

    // launch #1, #2 (gemm1 of layer 0 is launch #6 => ncu -s 5 -c 1 profiles it)
    init_h_kernel<<<elem_blocks, 256>>>(x, ae, h);
    zero_kernel<<<elem_blocks, 256>>>(agg, stats);

    for (int l = 0; l < Ll; l++) {
        transpose_w_kernel<<<128, 256>>>(W1 + (size_t)l * 128 * 256, wt1h, wt1l, 128, 256);
        transpose_w_kernel<<<128, 256>>>(W2 + (size_t)l * 256 * 128, wt2h, wt2l, 256, 128);

        edge_kernel<<<2048, 256>>>(h, be + (size_t)l * 3 * 8 * 128, ei, ea, ew, agg);

        dim3 grid1(gemm_blocks, 2);
        mma_gemm<128, 256, 0><<<grid1, 256, DSMEM>>>(
            h, agg, eps, l, sc1, wt1h, wt1l, b1 + l * 256, t1, st1);
        finalize_bn<<<1, 256>>>(st1, g1 + l * 256, bt1 + l * 256, sc1, 256);

        dim3 grid2(gemm_blocks, 1);
        mma_gemm<256, 128, 1><<<grid2, 256, DSMEM>>>(
            t1, (const float*)nullptr, (const float*)nullptr, 0, sc1,
            wt2h, wt2l, b2 + l * 128, t2, st2);
        finalize_bn<<<1, 128>>>(st2, go + l * 128, bto + l * 128, sc2, 128);

        float* dsth = (l == Ll - 1) ? out : h;
        apply_bn<<<elem_blocks, 256>>>(t2, sc2, dsth, (l < Ll - 1) ? 1 : 0,
                                       (l < Ll - 1) ? agg : (float*)nullptr);
    }
}

// round 9
// speedup vs baseline: 2.3397x; 1.2692x over previous
#include <cuda_runtime.h>
#include <cuda_bf16.h>
#include <cstdint>
#include <cstddef>

#define Nn 100000
#define Ee 500000
#define Ll 5

// -------- scratch (device globals: allocation-free) --------
__device__ __align__(16) float g_h[(size_t)Nn * 128];
__device__ __align__(16) float g_agg[(size_t)Nn * 128];
__device__ __align__(16) float g_t1[(size_t)Nn * 256];
__device__ __align__(16) float g_t2[(size_t)Nn * 128];
__device__ __align__(16) __nv_bfloat16 g_wt1_hi[5 * 256 * 128];
__device__ __align__(16) __nv_bfloat16 g_wt1_lo[5 * 256 * 128];
__device__ __align__(16) __nv_bfloat16 g_wt2_hi[5 * 128 * 256];
__device__ __align__(16) __nv_bfloat16 g_wt2_lo[5 * 128 * 256];
__device__ float g_stats[768];
__device__ float g_sc1[512];
__device__ float g_sc2[256];

// ======================= PTX helpers =======================
__device__ __forceinline__ void mma_bf16(float* c, const uint32_t* a, uint32_t b0, uint32_t b1) {
    asm volatile(
        "mma.sync.aligned.m16n8k16.row.col.f32.bf16.bf16.f32 "
        "{%0,%1,%2,%3}, {%4,%5,%6,%7}, {%8,%9}, {%0,%1,%2,%3};"
        : "+f"(c[0]), "+f"(c[1]), "+f"(c[2]), "+f"(c[3])
        : "r"(a[0]), "r"(a[1]), "r"(a[2]), "r"(a[3]), "r"(b0), "r"(b1));
}
__device__ __forceinline__ void ldsm4(uint32_t addr, uint32_t* r) {
    asm volatile("ldmatrix.sync.aligned.m8n8.x4.shared.b16 {%0,%1,%2,%3}, [%4];"
                 : "=r"(r[0]), "=r"(r[1]), "=r"(r[2]), "=r"(r[3]) : "r"(addr));
}
#define CP_ASYNC16(dst, src) \
    asm volatile("cp.async.cg.shared.global [%0], [%1], 16;" :: "r"(dst), "l"(src))
#define CP_COMMIT() asm volatile("cp.async.commit_group;" ::: "memory")
#define CP_WAIT0()  asm volatile("cp.async.wait_group 0;" ::: "memory")

// ======================= small kernels =======================
__global__ void init_h_kernel(const int* __restrict__ x,
                              const float* __restrict__ ae,
                              float* __restrict__ h) {
    int idx = blockIdx.x * blockDim.x + threadIdx.x;
    if (idx >= Nn * 128) return;
    int n = idx >> 7, d = idx & 127;
    float s = 0.f;
#pragma unroll
    for (int f = 0; f < 9; f++) {
        int xi = __ldg(x + n * 9 + f);
        s += __ldg(ae + (((size_t)(f * 120 + xi)) << 7) + d);
    }
    h[idx] = s;
}

__global__ void zero_kernel(float* __restrict__ agg, float* __restrict__ stats) {
    int idx = blockIdx.x * blockDim.x + threadIdx.x;
    if (stats && idx < 768) stats[idx] = 0.f;
    if (idx < Nn * 128) agg[idx] = 0.f;
}

// edge scatter. If sc != nullptr: source is t2 and h-value = relu(sc*t2+sh).
__global__ void __launch_bounds__(256) edge_kernel(
    const float* __restrict__ src_mat, const float* __restrict__ sc,
    const float* __restrict__ be,
    const int* __restrict__ ei, const int* __restrict__ ea,
    const float* __restrict__ ew, float* __restrict__ agg)
{
    __shared__ __align__(16) float sbe[3 * 8 * 128];
    __shared__ float ssc[128], ssh[128];
    for (int i = threadIdx.x; i < 3 * 8 * 128; i += 256) sbe[i] = be[i];
    if (sc && threadIdx.x < 128) {
        ssc[threadIdx.x] = sc[threadIdx.x];
        ssh[threadIdx.x] = sc[128 + threadIdx.x];
    }
    __syncthreads();

    int gwarp = (blockIdx.x * 256 + threadIdx.x) >> 5;
    int lane  = threadIdx.x & 31;
    int nw    = (gridDim.x * 256) >> 5;
    int d0    = lane * 4;
    const bool fuse = sc != nullptr;
    float c0, c1, c2, c3, h0, h1, h2, h3;
    if (fuse) {
        c0 = ssc[d0]; c1 = ssc[d0 + 1]; c2 = ssc[d0 + 2]; c3 = ssc[d0 + 3];
        h0 = ssh[d0]; h1 = ssh[d0 + 1]; h2 = ssh[d0 + 2]; h3 = ssh[d0 + 3];
    }

    for (int e = gwarp; e < Ee; e += nw) {
        int src = __ldg(ei + e);
        int dst = __ldg(ei + Ee + e);
        int a0  = __ldg(ea + e * 3 + 0);
        int a1  = __ldg(ea + e * 3 + 1);
        int a2  = __ldg(ea + e * 3 + 2);
        float w = __ldg(ew + e);

        float4 hv = *(const float4*)(src_mat + (size_t)src * 128 + d0);
        if (fuse) {
            hv.x = fmaxf(fmaf(c0, hv.x, h0), 0.f);
            hv.y = fmaxf(fmaf(c1, hv.y, h1), 0.f);
            hv.z = fmaxf(fmaf(c2, hv.z, h2), 0.f);
            hv.w = fmaxf(fmaf(c3, hv.w, h3), 0.f);
        }
        const float4 e0 = *(const float4*)(sbe + (a0      ) * 128 + d0);
        const float4 e1 = *(const float4*)(sbe + (8  + a1 ) * 128 + d0);
        const float4 e2 = *(const float4*)(sbe + (16 + a2 ) * 128 + d0);

        float m0 = fmaxf(hv.x + e0.x + e1.x + e2.x, 0.f) * w;
        float m1 = fmaxf(hv.y + e0.y + e1.y + e2.y, 0.f) * w;
        float m2 = fmaxf(hv.z + e0.z + e1.z + e2.z, 0.f) * w;
        float m3 = fmaxf(hv.w + e0.w + e1.w + e2.w, 0.f) * w;

        float* p = agg + (size_t)dst * 128 + d0;
        asm volatile("red.global.add.v4.f32 [%0], {%1,%2,%3,%4};"
                     :: "l"(p), "f"(m0), "f"(m1), "f"(m2), "f"(m3) : "memory");
    }
}

// all-layer weight transpose+split: Wt[l][n][k] = split(W[l][k][n])
__global__ void transpose_all_kernel(const float* __restrict__ W,
                                     __nv_bfloat16* __restrict__ Wt_hi,
                                     __nv_bfloat16* __restrict__ Wt_lo,
                                     int K, int NC) {
    int idx = blockIdx.x * 256 + threadIdx.x;
    int per = K * NC;
    if (idx >= 5 * per) return;
    int l = idx / per, r = idx - l * per;
    int n = r / K, k = r - n * K;
    float w = __ldg(W + (size_t)l * per + (size_t)k * NC + n);
    __nv_bfloat16 hi = __float2bfloat16(w);
    Wt_hi[idx] = hi;
    Wt_lo[idx] = __float2bfloat16(w - __bfloat162float(hi));
}

__global__ void finalize_bn(float* __restrict__ stats,
                            const float* __restrict__ g,
                            const float* __restrict__ bt,
                            float* __restrict__ scsh, int Cc) {
    int c = blockIdx.x * blockDim.x + threadIdx.x;
    if (c >= Cc) return;
    const float inv = 1.0f / (float)Nn;
    float mu  = stats[c] * inv;
    float var = stats[Cc + c] * inv - mu * mu;
    float sc  = __ldg(g + c) * rsqrtf(var + 1e-5f);
    scsh[c]      = sc;
    scsh[Cc + c] = fmaf(-mu, sc, __ldg(bt + c));
    stats[c] = 0.f;
    stats[Cc + c] = 0.f;
}

// final output only: out = BN(t2), no relu
__global__ void apply_bn(const float* __restrict__ t2,
                         const float* __restrict__ scsh,
                         float* __restrict__ outp) {
    int idx = blockIdx.x * blockDim.x + threadIdx.x;
    if (idx >= Nn * 128) return;
    int c = idx & 127;
    outp[idx] = fmaf(scsh[c], t2[idx], scsh[128 + c]);
}

// ======================= pipelined bf16 hi/lo mma GEMM =======================
// MODE 0: X = (1+eps)*A + A2                      (layer-0 gemm1)
// MODE 1: X = relu(sc[k]*A + sh[k])               (gemm2, BN1+relu fused)
// MODE 2: X = (1+eps)*relu(sc[k]*A + sh[k]) + A2  (layer>=1 gemm1, BN2 fused)
template <int K, int NC, int MODE>
__global__ void __launch_bounds__(256, 2) mma_gemm(
    const float* __restrict__ A, const float* __restrict__ A2,
    const float* __restrict__ epsp, int layer,
    const float* __restrict__ scsh,
    const __nv_bfloat16* __restrict__ Wt_hi, const __nv_bfloat16* __restrict__ Wt_lo,
    const float* __restrict__ bias,
    float* __restrict__ C, float* __restrict__ stats)
{
    constexpr int CHUNKS = K / 32;
    constexpr int STG = 40960;
    constexpr int AH = 0, AL = 10240, BH = 20480, BL = 30720;
    // row stride 80 bytes (32 bf16 + 16B pad)

    extern __shared__ char dsm[];
    __shared__ float s_sum[128];
    __shared__ float s_sq[128];

    uint32_t sb;
    asm("{ .reg .u64 t; cvta.to.shared.u64 t, %1; cvt.u32.u64 %0, t; }" : "=r"(sb) : "l"(dsm));

    const int tid  = threadIdx.x;
    const int wid  = tid >> 5, lane = tid & 31;
    const int g    = lane >> 2, t4 = lane & 3;
    const int wm   = wid & 3;
    const int wn   = wid >> 2;
    const int rowBase = blockIdx.x * 128;
    const int colBase = blockIdx.y * 128;

    if (tid < 128) { s_sum[tid] = 0.f; s_sq[tid] = 0.f; }

    float alpha = 1.0f;
    if (MODE != 1) alpha = 1.0f + __ldg(epsp + layer);
    const float* shv = scsh + K;

    const int lr  = tid >> 1;
    const int lk  = (tid & 1) * 16;
    const int lkb = (tid & 1) * 32;

    const int aoff = (wm * 32 + ((lane >> 3) & 1) * 8 + (lane & 7)) * 80 + (lane >> 4) * 16;
    const int boff = (wn * 64 + (lane >> 4) * 8 + (lane & 7)) * 80 + ((lane >> 3) & 1) * 16;

    float acc[2][8][4];
#pragma unroll
    for (int mt = 0; mt < 2; mt++)
#pragma unroll
        for (int nt = 0; nt < 8; nt++)
#pragma unroll
            for (int j = 0; j < 4; j++) acc[mt][nt][j] = 0.f;

    const int rg = rowBase + lr;
    const bool rv = rg < Nn;

    float4 pre[4];
    auto loadA = [&](int c) {
        const float* Ap = A + (size_t)rg * K + c * 32 + lk;
#pragma unroll
        for (int q = 0; q < 4; q++) {
            float4 v = make_float4(0.f, 0.f, 0.f, 0.f);
            if (rv) {
                float4 av = *(const float4*)(Ap + q * 4);
                int kg = c * 32 + lk + q * 4;
                if (MODE == 0) {
                    const float4 gv = *(const float4*)(A2 + (size_t)rg * K + kg);
                    v.x = fmaf(alpha, av.x, gv.x);
                    v.y = fmaf(alpha, av.y, gv.y);
                    v.z = fmaf(alpha, av.z, gv.z);
                    v.w = fmaf(alpha, av.w, gv.w);
                } else if (MODE == 1) {
                    v.x = fmaxf(fmaf(__ldg(scsh + kg + 0), av.x, __ldg(shv + kg + 0)), 0.f);
                    v.y = fmaxf(fmaf(__ldg(scsh + kg + 1), av.y, __ldg(shv + kg + 1)), 0.f);
                    v.z = fmaxf(fmaf(__ldg(scsh + kg + 2), av.z, __ldg(shv + kg + 2)), 0.f);
                    v.w = fmaxf(fmaf(__ldg(scsh + kg + 3), av.w, __ldg(shv + kg + 3)), 0.f);
                } else {
                    const float4 gv = *(const float4*)(A2 + (size_t)rg * K + kg);
                    float t0 = fmaxf(fmaf(__ldg(scsh + kg + 0), av.x, __ldg(shv + kg + 0)), 0.f);
                    float t1 = fmaxf(fmaf(__ldg(scsh + kg + 1), av.y, __ldg(shv + kg + 1)), 0.f);
                    float t2v = fmaxf(fmaf(__ldg(scsh + kg + 2), av.z, __ldg(shv + kg + 2)), 0.f);
                    float t3 = fmaxf(fmaf(__ldg(scsh + kg + 3), av.w, __ldg(shv + kg + 3)), 0.f);
                    v.x = fmaf(alpha, t0, gv.x);
                    v.y = fmaf(alpha, t1, gv.y);
                    v.z = fmaf(alpha, t2v, gv.z);
                    v.w = fmaf(alpha, t3, gv.w);
                }
            }
            pre[q] = v;
        }
    };
    auto cpasyncB = [&](int c, int stage) {
        const int n = colBase + lr;
        const __nv_bfloat16* Wh = Wt_hi + (size_t)n * K + c * 32 + lk;
        const __nv_bfloat16* Wl = Wt_lo + (size_t)n * K + c * 32 + lk;
        uint32_t dh = sb + stage * STG + BH + lr * 80 + lkb;
        uint32_t dl = sb + stage * STG + BL + lr * 80 + lkb;
        CP_ASYNC16(dh, Wh);
        CP_ASYNC16(dh + 16, Wh + 8);
        CP_ASYNC16(dl, Wl);
        CP_ASYNC16(dl + 16, Wl + 8);
    };
    auto storeA = [&](int stage) {
        uint32_t hi_d[8], lo_d[8];
#pragma unroll
        for (int q = 0; q < 4; q++) {
            float4 v = pre[q];
            __nv_bfloat162 h0 = __floats2bfloat162_rn(v.x, v.y);
            __nv_bfloat162 h1 = __floats2bfloat162_rn(v.z, v.w);
            float rx = v.x - __bfloat162float(h0.x);
            float ry = v.y - __bfloat162float(h0.y);
            float rz = v.z - __bfloat162float(h1.x);
            float rw = v.w - __bfloat162float(h1.y);
            __nv_bfloat162 l0 = __floats2bfloat162_rn(rx, ry);
            __nv_bfloat162 l1 = __floats2bfloat162_rn(rz, rw);
            hi_d[q * 2 + 0] = *(uint32_t*)&h0;
            hi_d[q * 2 + 1] = *(uint32_t*)&h1;
            lo_d[q * 2 + 0] = *(uint32_t*)&l0;
            lo_d[q * 2 + 1] = *(uint32_t*)&l1;
        }
        char* ah = dsm + stage * STG + AH + lr * 80 + lkb;
        char* al = dsm + stage * STG + AL + lr * 80 + lkb;
        *(uint4*)(ah)      = make_uint4(hi_d[0], hi_d[1], hi_d[2], hi_d[3]);
        *(uint4*)(ah + 16) = make_uint4(hi_d[4], hi_d[5], hi_d[6], hi_d[7]);
        *(uint4*)(al)      = make_uint4(lo_d[0], lo_d[1], lo_d[2], lo_d[3]);
        *(uint4*)(al + 16) = make_uint4(lo_d[4], lo_d[5], lo_d[6], lo_d[7]);
    };

    loadA(0);
    cpasyncB(0, 0);
    CP_COMMIT();
    storeA(0);
    CP_WAIT0();
    __syncthreads();

    for (int c = 0; c < CHUNKS; c++) {
        const int cur = c & 1, nxt = (c + 1) & 1;
        const bool more = (c + 1) < CHUNKS;
        if (more) {
            loadA(c + 1);
            cpasyncB(c + 1, nxt);
            CP_COMMIT();
        }

        const uint32_t base = sb + cur * STG;
#pragma unroll
        for (int ks = 0; ks < 2; ks++) {
            const int kb = ks * 32;
            uint32_t ah[2][4], al2[2][4];
#pragma unroll
            for (int mt = 0; mt < 2; mt++) {
                ldsm4(base + AH + aoff + mt * 1280 + kb, ah[mt]);
                ldsm4(base + AL + aoff + mt * 1280 + kb, al2[mt]);
            }
#pragma unroll
            for (int p = 0; p < 4; p++) {
                uint32_t bh[4], bl[4];
                ldsm4(base + BH + boff + p * 1280 + kb, bh);
                ldsm4(base + BL + boff + p * 1280 + kb, bl);
                // term-major order: dependent MMAs to same acc are 4 apart
#pragma unroll
                for (int mt = 0; mt < 2; mt++) {
                    mma_bf16(acc[mt][2 * p],     al2[mt], bh[0], bh[1]);
                    mma_bf16(acc[mt][2 * p + 1], al2[mt], bh[2], bh[3]);
                }
#pragma unroll
                for (int mt = 0; mt < 2; mt++) {
                    mma_bf16(acc[mt][2 * p],     ah[mt], bl[0], bl[1]);
                    mma_bf16(acc[mt][2 * p + 1], ah[mt], bl[2], bl[3]);
                }
#pragma unroll
                for (int mt = 0; mt < 2; mt++) {
                    mma_bf16(acc[mt][2 * p],     ah[mt], bh[0], bh[1]);
                    mma_bf16(acc[mt][2 * p + 1], ah[mt], bh[2], bh[3]);
                }
            }
        }

        if (more) storeA(nxt);
        CP_WAIT0();
        __syncthreads();
    }

    // ---- epilogue ----
#pragma unroll
    for (int nt = 0; nt < 8; nt++) {
        int cl = wn * 64 + nt * 8 + t4 * 2;
        float b0 = __ldg(bias + colBase + cl);
        float b1 = __ldg(bias + colBase + cl + 1);
        float cs0 = 0.f, cq0 = 0.f, cs1 = 0.f, cq1 = 0.f;
#pragma unroll
        for (int mt = 0; mt < 2; mt++) {
            int r0 = rowBase + wm * 32 + mt * 16 + g;
#pragma unroll
            for (int half = 0; half < 2; half++) {
                int rr = r0 + half * 8;
                float v0 = acc[mt][nt][half * 2] + b0;
                float v1 = acc[mt][nt][half * 2 + 1] + b1;
                if (rr < Nn) {
                    *(float2*)(C + (size_t)rr * NC + colBase + cl) = make_float2(v0, v1);
                    cs0 += v0; cq0 += v0 * v0;
                    cs1 += v1; cq1 += v1 * v1;
                }
            }
        }
#pragma unroll
        for (int o = 4; o <= 16; o <<= 1) {
            cs0 += __shfl_xor_sync(0xFFFFFFFFu, cs0, o);
            cq0 += __shfl_xor_sync(0xFFFFFFFFu, cq0, o);
            cs1 += __shfl_xor_sync(0xFFFFFFFFu, cs1, o);
            cq1 += __shfl_xor_sync(0xFFFFFFFFu, cq1, o);
        }
        if (g == 0) {
            atomicAdd(&s_sum[cl], cs0);
            atomicAdd(&s_sq[cl], cq0);
            atomicAdd(&s_sum[cl + 1], cs1);
            atomicAdd(&s_sq[cl + 1], cq1);
        }
    }
    __syncthreads();
    if (tid < 128) {
        atomicAdd(&stats[colBase + tid],      s_sum[tid]);
        atomicAdd(&stats[NC + colBase + tid], s_sq[tid]);
    }
}

// ======================= launch =======================
extern "C" void kernel_launch(void* const* d_in, const int* in_sizes, int n_in,
                              void* d_out, int out_size) {
    const int*   x    = (const int*)d_in[0];
    const int*   ei   = (const int*)d_in[1];
    const int*   ea   = (const int*)d_in[2];
    const float* ew   = (const float*)d_in[3];
    const float* ae   = (const float*)d_in[4];
    const float* be   = (const float*)d_in[5];
    const float* eps  = (const float*)d_in[6];
    const float* W1   = (const float*)d_in[7];
    const float* b1   = (const float*)d_in[8];
    const float* g1   = (const float*)d_in[9];
    const float* bt1  = (const float*)d_in[10];
    const float* W2   = (const float*)d_in[11];
    const float* b2   = (const float*)d_in[12];
    const float* go   = (const float*)d_in[13];
    const float* bto  = (const float*)d_in[14];
    float* out = (float*)d_out;

    float *h, *agg, *t1, *t2, *stats, *sc1, *sc2;
    __nv_bfloat16 *wt1h, *wt1l, *wt2h, *wt2l;
    cudaGetSymbolAddress((void**)&h,     g_h);
    cudaGetSymbolAddress((void**)&agg,   g_agg);
    cudaGetSymbolAddress((void**)&t1,    g_t1);
    cudaGetSymbolAddress((void**)&t2,    g_t2);
    cudaGetSymbolAddress((void**)&wt1h,  g_wt1_hi);
    cudaGetSymbolAddress((void**)&wt1l,  g_wt1_lo);
    cudaGetSymbolAddress((void**)&wt2h,  g_wt2_hi);
    cudaGetSymbolAddress((void**)&wt2l,  g_wt2_lo);
    cudaGetSymbolAddress((void**)&stats, g_stats);
    cudaGetSymbolAddress((void**)&sc1,   g_sc1);
    cudaGetSymbolAddress((void**)&sc2,   g_sc2);
    float* st1 = stats;
    float* st2 = stats + 512;

    const int DSMEM = 2 * 40960;
    cudaFuncSetAttribute(mma_gemm<128, 256, 0>,
                         cudaFuncAttributeMaxDynamicSharedMemorySize, DSMEM);
    cudaFuncSetAttribute(mma_gemm<128, 256, 2>,
                         cudaFuncAttributeMaxDynamicSharedMemorySize, DSMEM);
    cudaFuncSetAttribute(mma_gemm<256, 128, 1>,
                         cudaFuncAttributeMaxDynamicSharedMemorySize, DSMEM);

    const int elem_blocks = (Nn * 128 + 255) / 256;
    const int gemm_blocks = (Nn + 127) / 128;

    init_h_kernel<<<elem_blocks, 256>>>(x, ae, h);
    zero_kernel<<<elem_blocks, 256>>>(agg, stats);
    transpose_all_kernel<<<(5 * 128 * 256 + 255) / 256, 256>>>(W1, wt1h, wt1l, 128, 256);
    transpose_all_kernel<<<(5 * 128 * 256 + 255) / 256, 256>>>(W2, wt2h, wt2l, 256, 128);

    for (int l = 0; l < Ll; l++) {
        const size_t wo = (size_t)l * 128 * 256;
        if (l == 0) {
            edge_kernel<<<2048, 256>>>(h, (const float*)nullptr,
                                       be + (size_t)l * 3 * 8 * 128, ei, ea, ew, agg);
            dim3 grid1(gemm_blocks, 2);
            mma_gemm<128, 256, 0><<<grid1, 256, DSMEM>>>(
                h, agg, eps, l, (const float*)nullptr,
                wt1h + wo, wt1l + wo, b1 + l * 256, t1, st1);
        } else {
            zero_kernel<<<elem_blocks, 256>>>(agg, (float*)nullptr);
            edge_kernel<<<2048, 256>>>(t2, sc2,
                                       be + (size_t)l * 3 * 8 * 128, ei, ea, ew, agg);
            dim3 grid1(gemm_blocks, 2);
            mma_gemm<128, 256, 2><<<grid1, 256, DSMEM>>>(
                t2, agg, eps, l, sc2,
                wt1h + wo, wt1l + wo, b1 + l * 256, t1, st1);
        }
        finalize_bn<<<1, 256>>>(st1, g1 + l * 256, bt1 + l * 256, sc1, 256);

        dim3 grid2(gemm_blocks, 1);
        mma_gemm<256, 128, 1><<<grid2, 256, DSMEM>>>(
            t1, (const float*)nullptr, (const float*)nullptr, 0, sc1,
            wt2h + wo, wt2l + wo, b2 + l * 128, t2, st2);
        finalize_bn<<<1, 128>>>(st2, go + l * 128, bto + l * 128, sc2, 128);
    }
    apply_bn<<<elem_blocks, 256>>>(t2, sc2, out);
}

// round 10
// speedup vs baseline: 2.3977x; 1.0248x over previous
#include <cuda_runtime.h>
#include <cuda_bf16.h>
#include <cstdint>
#include <cstddef>

#define Nn 100000
#define Ee 500000
#define Ll 5

// -------- scratch (device globals: allocation-free) --------
__device__ __align__(16) float g_h[(size_t)Nn * 128];
__device__ __align__(16) float g_agg[(size_t)Nn * 128];
__device__ __align__(16) float g_t1[(size_t)Nn * 256];
__device__ __align__(16) float g_t2[(size_t)Nn * 128];
__device__ __align__(16) __nv_bfloat16 g_wt1_hi[5 * 256 * 128];
__device__ __align__(16) __nv_bfloat16 g_wt1_lo[5 * 256 * 128];
__device__ __align__(16) __nv_bfloat16 g_wt2_hi[5 * 128 * 256];
__device__ __align__(16) __nv_bfloat16 g_wt2_lo[5 * 128 * 256];
__device__ float g_stats[768];
__device__ float g_sc1[512];
__device__ float g_sc2[256];
// CSR scratch
__device__ int g_deg[Nn];
__device__ int g_rowptr[Nn + 1];
__device__ int g_cursor[Nn + 1];
__device__ int g_perm[Ee];
__device__ int g_code[Ee];
__device__ __align__(16) float g_esum[512 * 128];

// ======================= PTX helpers =======================
__device__ __forceinline__ void mma_bf16(float* c, const uint32_t* a, uint32_t b0, uint32_t b1) {
    asm volatile(
        "mma.sync.aligned.m16n8k16.row.col.f32.bf16.bf16.f32 "
        "{%0,%1,%2,%3}, {%4,%5,%6,%7}, {%8,%9}, {%0,%1,%2,%3};"
        : "+f"(c[0]), "+f"(c[1]), "+f"(c[2]), "+f"(c[3])
        : "r"(a[0]), "r"(a[1]), "r"(a[2]), "r"(a[3]), "r"(b0), "r"(b1));
}
__device__ __forceinline__ void ldsm4(uint32_t addr, uint32_t* r) {
    asm volatile("ldmatrix.sync.aligned.m8n8.x4.shared.b16 {%0,%1,%2,%3}, [%4];"
                 : "=r"(r[0]), "=r"(r[1]), "=r"(r[2]), "=r"(r[3]) : "r"(addr));
}
#define CP_ASYNC16(dst, src) \
    asm volatile("cp.async.cg.shared.global [%0], [%1], 16;" :: "r"(dst), "l"(src))
#define CP_COMMIT() asm volatile("cp.async.commit_group;" ::: "memory")
#define CP_WAIT0()  asm volatile("cp.async.wait_group 0;" ::: "memory")

// ======================= CSR build =======================
__global__ void hist_kernel(const int* __restrict__ ei, const int* __restrict__ ea,
                            int* __restrict__ deg, int* __restrict__ code) {
    int e = blockIdx.x * 256 + threadIdx.x;
    if (e >= Ee) return;
    atomicAdd(&deg[__ldg(ei + Ee + e)], 1);
    int a0 = __ldg(ea + e * 3 + 0);
    int a1 = __ldg(ea + e * 3 + 1);
    int a2 = __ldg(ea + e * 3 + 2);
    code[e] = (a0 * 8 + a1) * 8 + a2;
}

// single-block looped inclusive scan -> rowptr (exclusive) + cursor copy
__global__ void scan_kernel(const int* __restrict__ deg,
                            int* __restrict__ rowptr, int* __restrict__ cursor) {
    __shared__ int s[1024];
    __shared__ int carry_s;
    int tid = threadIdx.x;
    if (tid == 0) { carry_s = 0; rowptr[0] = 0; cursor[0] = 0; }
    __syncthreads();
    for (int base = 0; base < Nn; base += 1024) {
        int i = base + tid;
        int v = (i < Nn) ? deg[i] : 0;
        s[tid] = v;
        __syncthreads();
#pragma unroll
        for (int off = 1; off < 1024; off <<= 1) {
            int t = (tid >= off) ? s[tid - off] : 0;
            __syncthreads();
            s[tid] += t;
            __syncthreads();
        }
        int c0 = carry_s;
        int incl = s[tid] + c0;
        if (i < Nn) { rowptr[i + 1] = incl; cursor[i + 1] = incl; }
        __syncthreads();
        if (tid == 0) carry_s = c0 + s[1023];
        __syncthreads();
    }
}

__global__ void fill_kernel(const int* __restrict__ ei,
                            int* __restrict__ cursor, int* __restrict__ perm) {
    int e = blockIdx.x * 256 + threadIdx.x;
    if (e >= Ee) return;
    int pos = atomicAdd(&cursor[__ldg(ei + Ee + e)], 1);
    perm[pos] = e;
}

// esum[c][d] = sum_f be[f][a_f][d] for code c (per layer)
__global__ void esum_kernel(const float* __restrict__ be, float* __restrict__ esum) {
    int idx = blockIdx.x * 256 + threadIdx.x;   // < 512*128
    int c = idx >> 7, d = idx & 127;
    int a0 = c >> 6, a1 = (c >> 3) & 7, a2 = c & 7;
    esum[idx] = __ldg(be + a0 * 128 + d) + __ldg(be + (8 + a1) * 128 + d)
              + __ldg(be + (16 + a2) * 128 + d);
}

// ======================= small kernels =======================
__global__ void init_h_kernel(const int* __restrict__ x,
                              const float* __restrict__ ae,
                              float* __restrict__ h) {
    int idx = blockIdx.x * blockDim.x + threadIdx.x;
    if (idx >= Nn * 128) return;
    int n = idx >> 7, d = idx & 127;
    float s = 0.f;
#pragma unroll
    for (int f = 0; f < 9; f++) {
        int xi = __ldg(x + n * 9 + f);
        s += __ldg(ae + (((size_t)(f * 120 + xi)) << 7) + d);
    }
    h[idx] = s;
}

// warp-per-node gather aggregation. If sc != nullptr: h-value = relu(sc*src+sh).
__global__ void __launch_bounds__(256) edge_agg_kernel(
    const float* __restrict__ src_mat, const float* __restrict__ sc,
    const float* __restrict__ esum,
    const int* __restrict__ rowptr, const int* __restrict__ perm,
    const int* __restrict__ ei, const int* __restrict__ code,
    const float* __restrict__ ew, float* __restrict__ agg)
{
    __shared__ float ssc[128], ssh[128];
    if (sc && threadIdx.x < 128) {
        ssc[threadIdx.x] = sc[threadIdx.x];
        ssh[threadIdx.x] = sc[128 + threadIdx.x];
    }
    __syncthreads();

    int node = (blockIdx.x * 256 + threadIdx.x) >> 5;   // 100000 warps exactly
    int lane = threadIdx.x & 31;
    int d0 = lane * 4;
    const bool fuse = sc != nullptr;
    float c0, c1, c2, c3, s0, s1, s2, s3;
    if (fuse) {
        c0 = ssc[d0]; c1 = ssc[d0 + 1]; c2 = ssc[d0 + 2]; c3 = ssc[d0 + 3];
        s0 = ssh[d0]; s1 = ssh[d0 + 1]; s2 = ssh[d0 + 2]; s3 = ssh[d0 + 3];
    }

    float a0 = 0.f, a1 = 0.f, a2 = 0.f, a3 = 0.f;
    int beg = __ldg(rowptr + node), end = __ldg(rowptr + node + 1);
    for (int i = beg; i < end; i++) {
        int e   = __ldg(perm + i);
        int src = __ldg(ei + e);
        int cd  = __ldg(code + e);
        float w = __ldg(ew + e);
        float4 hv = *(const float4*)(src_mat + (size_t)src * 128 + d0);
        if (fuse) {
            hv.x = fmaxf(fmaf(c0, hv.x, s0), 0.f);
            hv.y = fmaxf(fmaf(c1, hv.y, s1), 0.f);
            hv.z = fmaxf(fmaf(c2, hv.z, s2), 0.f);
            hv.w = fmaxf(fmaf(c3, hv.w, s3), 0.f);
        }
        const float4 ev = *(const float4*)(esum + (size_t)cd * 128 + d0);
        a0 = fmaf(fmaxf(hv.x + ev.x, 0.f), w, a0);
        a1 = fmaf(fmaxf(hv.y + ev.y, 0.f), w, a1);
        a2 = fmaf(fmaxf(hv.z + ev.z, 0.f), w, a2);
        a3 = fmaf(fmaxf(hv.w + ev.w, 0.f), w, a3);
    }
    *(float4*)(agg + (size_t)node * 128 + d0) = make_float4(a0, a1, a2, a3);
}

// all-layer weight transpose+split
__global__ void transpose_all_kernel(const float* __restrict__ W,
                                     __nv_bfloat16* __restrict__ Wt_hi,
                                     __nv_bfloat16* __restrict__ Wt_lo,
                                     int K, int NC) {
    int idx = blockIdx.x * 256 + threadIdx.x;
    int per = K * NC;
    if (idx >= 5 * per) return;
    int l = idx / per, r = idx - l * per;
    int n = r / K, k = r - n * K;
    float w = __ldg(W + (size_t)l * per + (size_t)k * NC + n);
    __nv_bfloat16 hi = __float2bfloat16(w);
    Wt_hi[idx] = hi;
    Wt_lo[idx] = __float2bfloat16(w - __bfloat162float(hi));
}

__global__ void finalize_bn(float* __restrict__ stats,
                            const float* __restrict__ g,
                            const float* __restrict__ bt,
                            float* __restrict__ scsh, int Cc) {
    int c = blockIdx.x * blockDim.x + threadIdx.x;
    if (c >= Cc) return;
    const float inv = 1.0f / (float)Nn;
    float mu  = stats[c] * inv;
    float var = stats[Cc + c] * inv - mu * mu;
    float sc  = __ldg(g + c) * rsqrtf(var + 1e-5f);
    scsh[c]      = sc;
    scsh[Cc + c] = fmaf(-mu, sc, __ldg(bt + c));
    stats[c] = 0.f;
    stats[Cc + c] = 0.f;
}

__global__ void apply_bn(const float* __restrict__ t2,
                         const float* __restrict__ scsh,
                         float* __restrict__ outp) {
    int idx = blockIdx.x * blockDim.x + threadIdx.x;
    if (idx >= Nn * 128) return;
    int c = idx & 127;
    outp[idx] = fmaf(scsh[c], t2[idx], scsh[128 + c]);
}

// ======================= pipelined bf16 hi/lo mma GEMM =======================
// MODE 0: X = (1+eps)*A + A2
// MODE 1: X = relu(sc[k]*A + sh[k])
// MODE 2: X = (1+eps)*relu(sc[k]*A + sh[k]) + A2
template <int K, int NC, int MODE>
__global__ void __launch_bounds__(256, 2) mma_gemm(
    const float* __restrict__ A, const float* __restrict__ A2,
    const float* __restrict__ epsp, int layer,
    const float* __restrict__ scsh,
    const __nv_bfloat16* __restrict__ Wt_hi, const __nv_bfloat16* __restrict__ Wt_lo,
    const float* __restrict__ bias,
    float* __restrict__ C, float* __restrict__ stats)
{
    constexpr int CHUNKS = K / 32;
    constexpr int STG = 40960;
    constexpr int AH = 0, AL = 10240, BH = 20480, BL = 30720;

    extern __shared__ char dsm[];
    __shared__ float s_sum[128];
    __shared__ float s_sq[128];

    uint32_t sb;
    asm("{ .reg .u64 t; cvta.to.shared.u64 t, %1; cvt.u32.u64 %0, t; }" : "=r"(sb) : "l"(dsm));

    const int tid  = threadIdx.x;
    const int wid  = tid >> 5, lane = tid & 31;
    const int g    = lane >> 2, t4 = lane & 3;
    const int wm   = wid & 3;
    const int wn   = wid >> 2;
    const int rowBase = blockIdx.x * 128;
    const int colBase = blockIdx.y * 128;

    if (tid < 128) { s_sum[tid] = 0.f; s_sq[tid] = 0.f; }

    float alpha = 1.0f;
    if (MODE != 1) alpha = 1.0f + __ldg(epsp + layer);
    const float* shv = scsh + K;

    const int lr  = tid >> 1;
    const int lk  = (tid & 1) * 16;
    const int lkb = (tid & 1) * 32;

    const int aoff = (wm * 32 + ((lane >> 3) & 1) * 8 + (lane & 7)) * 80 + (lane >> 4) * 16;
    const int boff = (wn * 64 + (lane >> 4) * 8 + (lane & 7)) * 80 + ((lane >> 3) & 1) * 16;

    float acc[2][8][4];
#pragma unroll
    for (int mt = 0; mt < 2; mt++)
#pragma unroll
        for (int nt = 0; nt < 8; nt++)
#pragma unroll
            for (int j = 0; j < 4; j++) acc[mt][nt][j] = 0.f;

    const int rg = rowBase + lr;
    const bool rv = rg < Nn;

    float4 pre[4];
    auto loadA = [&](int c) {
        const float* Ap = A + (size_t)rg * K + c * 32 + lk;
#pragma unroll
        for (int q = 0; q < 4; q++) {
            float4 v = make_float4(0.f, 0.f, 0.f, 0.f);
            if (rv) {
                float4 av = *(const float4*)(Ap + q * 4);
                int kg = c * 32 + lk + q * 4;
                if (MODE == 0) {
                    const float4 gv = *(const float4*)(A2 + (size_t)rg * K + kg);
                    v.x = fmaf(alpha, av.x, gv.x);
                    v.y = fmaf(alpha, av.y, gv.y);
                    v.z = fmaf(alpha, av.z, gv.z);
                    v.w = fmaf(alpha, av.w, gv.w);
                } else if (MODE == 1) {
                    v.x = fmaxf(fmaf(__ldg(scsh + kg + 0), av.x, __ldg(shv + kg + 0)), 0.f);
                    v.y = fmaxf(fmaf(__ldg(scsh + kg + 1), av.y, __ldg(shv + kg + 1)), 0.f);
                    v.z = fmaxf(fmaf(__ldg(scsh + kg + 2), av.z, __ldg(shv + kg + 2)), 0.f);
                    v.w = fmaxf(fmaf(__ldg(scsh + kg + 3), av.w, __ldg(shv + kg + 3)), 0.f);
                } else {
                    const float4 gv = *(const float4*)(A2 + (size_t)rg * K + kg);
                    float t0 = fmaxf(fmaf(__ldg(scsh + kg + 0), av.x, __ldg(shv + kg + 0)), 0.f);
                    float t1 = fmaxf(fmaf(__ldg(scsh + kg + 1), av.y, __ldg(shv + kg + 1)), 0.f);
                    float t2v = fmaxf(fmaf(__ldg(scsh + kg + 2), av.z, __ldg(shv + kg + 2)), 0.f);
                    float t3 = fmaxf(fmaf(__ldg(scsh + kg + 3), av.w, __ldg(shv + kg + 3)), 0.f);
                    v.x = fmaf(alpha, t0, gv.x);
                    v.y = fmaf(alpha, t1, gv.y);
                    v.z = fmaf(alpha, t2v, gv.z);
                    v.w = fmaf(alpha, t3, gv.w);
                }
            }
            pre[q] = v;
        }
    };
    auto cpasyncB = [&](int c, int stage) {
        const int n = colBase + lr;
        const __nv_bfloat16* Wh = Wt_hi + (size_t)n * K + c * 32 + lk;
        const __nv_bfloat16* Wl = Wt_lo + (size_t)n * K + c * 32 + lk;
        uint32_t dh = sb + stage * STG + BH + lr * 80 + lkb;
        uint32_t dl = sb + stage * STG + BL + lr * 80 + lkb;
        CP_ASYNC16(dh, Wh);
        CP_ASYNC16(dh + 16, Wh + 8);
        CP_ASYNC16(dl, Wl);
        CP_ASYNC16(dl + 16, Wl + 8);
    };
    auto storeA = [&](int stage) {
        uint32_t hi_d[8], lo_d[8];
#pragma unroll
        for (int q = 0; q < 4; q++) {
            float4 v = pre[q];
            __nv_bfloat162 h0 = __floats2bfloat162_rn(v.x, v.y);
            __nv_bfloat162 h1 = __floats2bfloat162_rn(v.z, v.w);
            float rx = v.x - __bfloat162float(h0.x);
            float ry = v.y - __bfloat162float(h0.y);
            float rz = v.z - __bfloat162float(h1.x);
            float rw = v.w - __bfloat162float(h1.y);
            __nv_bfloat162 l0 = __floats2bfloat162_rn(rx, ry);
            __nv_bfloat162 l1 = __floats2bfloat162_rn(rz, rw);
            hi_d[q * 2 + 0] = *(uint32_t*)&h0;
            hi_d[q * 2 + 1] = *(uint32_t*)&h1;
            lo_d[q * 2 + 0] = *(uint32_t*)&l0;
            lo_d[q * 2 + 1] = *(uint32_t*)&l1;
        }
        char* ah = dsm + stage * STG + AH + lr * 80 + lkb;
        char* al = dsm + stage * STG + AL + lr * 80 + lkb;
        *(uint4*)(ah)      = make_uint4(hi_d[0], hi_d[1], hi_d[2], hi_d[3]);
        *(uint4*)(ah + 16) = make_uint4(hi_d[4], hi_d[5], hi_d[6], hi_d[7]);
        *(uint4*)(al)      = make_uint4(lo_d[0], lo_d[1], lo_d[2], lo_d[3]);
        *(uint4*)(al + 16) = make_uint4(lo_d[4], lo_d[5], lo_d[6], lo_d[7]);
    };

    loadA(0);
    cpasyncB(0, 0);
    CP_COMMIT();
    storeA(0);
    CP_WAIT0();
    __syncthreads();

    for (int c = 0; c < CHUNKS; c++) {
        const int cur = c & 1, nxt = (c + 1) & 1;
        const bool more = (c + 1) < CHUNKS;
        if (more) {
            loadA(c + 1);
            cpasyncB(c + 1, nxt);
            CP_COMMIT();
        }

        const uint32_t base = sb + cur * STG;
#pragma unroll
        for (int ks = 0; ks < 2; ks++) {
            const int kb = ks * 32;
            uint32_t ah[2][4], al2[2][4];
#pragma unroll
            for (int mt = 0; mt < 2; mt++) {
                ldsm4(base + AH + aoff + mt * 1280 + kb, ah[mt]);
                ldsm4(base + AL + aoff + mt * 1280 + kb, al2[mt]);
            }
#pragma unroll
            for (int p = 0; p < 4; p++) {
                uint32_t bh[4], bl[4];
                ldsm4(base + BH + boff + p * 1280 + kb, bh);
                ldsm4(base + BL + boff + p * 1280 + kb, bl);
#pragma unroll
                for (int mt = 0; mt < 2; mt++) {
                    mma_bf16(acc[mt][2 * p],     al2[mt], bh[0], bh[1]);
                    mma_bf16(acc[mt][2 * p + 1], al2[mt], bh[2], bh[3]);
                }
#pragma unroll
                for (int mt = 0; mt < 2; mt++) {
                    mma_bf16(acc[mt][2 * p],     ah[mt], bl[0], bl[1]);
                    mma_bf16(acc[mt][2 * p + 1], ah[mt], bl[2], bl[3]);
                }
#pragma unroll
                for (int mt = 0; mt < 2; mt++) {
                    mma_bf16(acc[mt][2 * p],     ah[mt], bh[0], bh[1]);
                    mma_bf16(acc[mt][2 * p + 1], ah[mt], bh[2], bh[3]);
                }
            }
        }

        if (more) storeA(nxt);
        CP_WAIT0();
        __syncthreads();
    }

    // ---- epilogue ----
#pragma unroll
    for (int nt = 0; nt < 8; nt++) {
        int cl = wn * 64 + nt * 8 + t4 * 2;
        float b0 = __ldg(bias + colBase + cl);
        float b1 = __ldg(bias + colBase + cl + 1);
        float cs0 = 0.f, cq0 = 0.f, cs1 = 0.f, cq1 = 0.f;
#pragma unroll
        for (int mt = 0; mt < 2; mt++) {
            int r0 = rowBase + wm * 32 + mt * 16 + g;
#pragma unroll
            for (int half = 0; half < 2; half++) {
                int rr = r0 + half * 8;
                float v0 = acc[mt][nt][half * 2] + b0;
                float v1 = acc[mt][nt][half * 2 + 1] + b1;
                if (rr < Nn) {
                    *(float2*)(C + (size_t)rr * NC + colBase + cl) = make_float2(v0, v1);
                    cs0 += v0; cq0 += v0 * v0;
                    cs1 += v1; cq1 += v1 * v1;
                }
            }
        }
#pragma unroll
        for (int o = 4; o <= 16; o <<= 1) {
            cs0 += __shfl_xor_sync(0xFFFFFFFFu, cs0, o);
            cq0 += __shfl_xor_sync(0xFFFFFFFFu, cq0, o);
            cs1 += __shfl_xor_sync(0xFFFFFFFFu, cs1, o);
            cq1 += __shfl_xor_sync(0xFFFFFFFFu, cq1, o);
        }
        if (g == 0) {
            atomicAdd(&s_sum[cl], cs0);
            atomicAdd(&s_sq[cl], cq0);
            atomicAdd(&s_sum[cl + 1], cs1);
            atomicAdd(&s_sq[cl + 1], cq1);
        }
    }
    __syncthreads();
    if (tid < 128) {
        atomicAdd(&stats[colBase + tid],      s_sum[tid]);
        atomicAdd(&stats[NC + colBase + tid], s_sq[tid]);
    }
}

// ======================= launch =======================
extern "C" void kernel_launch(void* const* d_in, const int* in_sizes, int n_in,
                              void* d_out, int out_size) {
    const int*   x    = (const int*)d_in[0];
    const int*   ei   = (const int*)d_in[1];
    const int*   ea   = (const int*)d_in[2];
    const float* ew   = (const float*)d_in[3];
    const float* ae   = (const float*)d_in[4];
    const float* be   = (const float*)d_in[5];
    const float* eps  = (const float*)d_in[6];
    const float* W1   = (const float*)d_in[7];
    const float* b1   = (const float*)d_in[8];
    const float* g1   = (const float*)d_in[9];
    const float* bt1  = (const float*)d_in[10];
    const float* W2   = (const float*)d_in[11];
    const float* b2   = (const float*)d_in[12];
    const float* go   = (const float*)d_in[13];
    const float* bto  = (const float*)d_in[14];
    float* out = (float*)d_out;

    float *h, *agg, *t1, *t2, *stats, *sc1, *sc2, *esum;
    __nv_bfloat16 *wt1h, *wt1l, *wt2h, *wt2l;
    int *deg, *rowptr, *cursor, *perm, *code;
    cudaGetSymbolAddress((void**)&h,      g_h);
    cudaGetSymbolAddress((void**)&agg,    g_agg);
    cudaGetSymbolAddress((void**)&t1,     g_t1);
    cudaGetSymbolAddress((void**)&t2,     g_t2);
    cudaGetSymbolAddress((void**)&wt1h,   g_wt1_hi);
    cudaGetSymbolAddress((void**)&wt1l,   g_wt1_lo);
    cudaGetSymbolAddress((void**)&wt2h,   g_wt2_hi);
    cudaGetSymbolAddress((void**)&wt2l,   g_wt2_lo);
    cudaGetSymbolAddress((void**)&stats,  g_stats);
    cudaGetSymbolAddress((void**)&sc1,    g_sc1);
    cudaGetSymbolAddress((void**)&sc2,    g_sc2);
    cudaGetSymbolAddress((void**)&deg,    g_deg);
    cudaGetSymbolAddress((void**)&rowptr, g_rowptr);
    cudaGetSymbolAddress((void**)&cursor, g_cursor);
    cudaGetSymbolAddress((void**)&perm,   g_perm);
    cudaGetSymbolAddress((void**)&code,   g_code);
    cudaGetSymbolAddress((void**)&esum,   g_esum);
    float* st1 = stats;
    float* st2 = stats + 512;

    const int DSMEM = 2 * 40960;
    cudaFuncSetAttribute(mma_gemm<128, 256, 0>,
                         cudaFuncAttributeMaxDynamicSharedMemorySize, DSMEM);
    cudaFuncSetAttribute(mma_gemm<128, 256, 2>,
                         cudaFuncAttributeMaxDynamicSharedMemorySize, DSMEM);
    cudaFuncSetAttribute(mma_gemm<256, 128, 1>,
                         cudaFuncAttributeMaxDynamicSharedMemorySize, DSMEM);

    const int elem_blocks = (Nn * 128 + 255) / 256;
    const int gemm_blocks = (Nn + 127) / 128;
    const int edge_blocks = (Ee + 255) / 256;

    // ---- one-time (per call) setup ----
    cudaMemsetAsync(deg, 0, Nn * sizeof(int));
    cudaMemsetAsync(stats, 0, 768 * sizeof(float));
    init_h_kernel<<<elem_blocks, 256>>>(x, ae, h);
    transpose_all_kernel<<<(5 * 128 * 256 + 255) / 256, 256>>>(W1, wt1h, wt1l, 128, 256);
    transpose_all_kernel<<<(5 * 128 * 256 + 255) / 256, 256>>>(W2, wt2h, wt2l, 256, 128);
    hist_kernel<<<edge_blocks, 256>>>(ei, ea, deg, code);
    scan_kernel<<<1, 1024>>>(deg, rowptr, cursor);
    fill_kernel<<<edge_blocks, 256>>>(ei, cursor, perm);

    for (int l = 0; l < Ll; l++) {
        const size_t wo = (size_t)l * 128 * 256;
        esum_kernel<<<512 * 128 / 256, 256>>>(be + (size_t)l * 3 * 8 * 128, esum);

        dim3 grid1(gemm_blocks, 2);
        if (l == 0) {
            edge_agg_kernel<<<Nn / 8, 256>>>(h, (const float*)nullptr, esum,
                                             rowptr, perm, ei, code, ew, agg);
            mma_gemm<128, 256, 0><<<grid1, 256, DSMEM>>>(
                h, agg, eps, l, (const float*)nullptr,
                wt1h + wo, wt1l + wo, b1 + l * 256, t1, st1);
        } else {
            edge_agg_kernel<<<Nn / 8, 256>>>(t2, sc2, esum,
                                             rowptr, perm, ei, code, ew, agg);
            mma_gemm<128, 256, 2><<<grid1, 256, DSMEM>>>(
                t2, agg, eps, l, sc2,
                wt1h + wo, wt1l + wo, b1 + l * 256, t1, st1);
        }
        finalize_bn<<<1, 256>>>(st1, g1 + l * 256, bt1 + l * 256, sc1, 256);

        dim3 grid2(gemm_blocks, 1);
        mma_gemm<256, 128, 1><<<grid2, 256, DSMEM>>>(
            t1, (const float*)nullptr, (const float*)nullptr, 0, sc1,
            wt2h + wo, wt2l + wo, b2 + l * 128, t2, st2);
        finalize_bn<<<1, 128>>>(st2, go + l * 128, bto + l * 128, sc2, 128);
    }
    apply_bn<<<elem_blocks, 256>>>(t2, sc2, out);
}

// round 13
// speedup vs baseline: 2.6181x; 1.0919x over previous
#include <cuda_runtime.h>
#include <cuda_bf16.h>
#include <cstdint>
#include <cstddef>

#define Nn 100000
#define Ee 500000
#define Ll 5

// -------- scratch (device globals: allocation-free) --------
__device__ __align__(16) float g_h[(size_t)Nn * 128];
__device__ __align__(16) float g_agg[(size_t)Nn * 128];
__device__ __align__(16) float g_t1[(size_t)Nn * 256];
__device__ __align__(16) float g_t2[(size_t)Nn * 128];
__device__ __align__(16) __nv_bfloat16 g_wt1_hi[5 * 256 * 128];
__device__ __align__(16) __nv_bfloat16 g_wt1_lo[5 * 256 * 128];
__device__ __align__(16) __nv_bfloat16 g_wt2_hi[5 * 128 * 256];
__device__ __align__(16) __nv_bfloat16 g_wt2_lo[5 * 128 * 256];
__device__ float g_stats[768];
__device__ float g_sc1[512];
__device__ float g_sc2[256];
// CSR scratch
__device__ int g_deg[Nn];
__device__ int g_rowptr[Nn + 1];
__device__ int g_cursor[Nn + 1];
__device__ int g_srcs[Ee];
__device__ int g_codes[Ee];
__device__ float g_ews[Ee];
__device__ int g_code[Ee];
__device__ __align__(16) float g_esum[5 * 512 * 128];

// ======================= PTX helpers =======================
__device__ __forceinline__ void mma_bf16(float* c, const uint32_t* a, uint32_t b0, uint32_t b1) {
    asm volatile(
        "mma.sync.aligned.m16n8k16.row.col.f32.bf16.bf16.f32 "
        "{%0,%1,%2,%3}, {%4,%5,%6,%7}, {%8,%9}, {%0,%1,%2,%3};"
        : "+f"(c[0]), "+f"(c[1]), "+f"(c[2]), "+f"(c[3])
        : "r"(a[0]), "r"(a[1]), "r"(a[2]), "r"(a[3]), "r"(b0), "r"(b1));
}
__device__ __forceinline__ void ldsm4(uint32_t addr, uint32_t* r) {
    asm volatile("ldmatrix.sync.aligned.m8n8.x4.shared.b16 {%0,%1,%2,%3}, [%4];"
                 : "=r"(r[0]), "=r"(r[1]), "=r"(r[2]), "=r"(r[3]) : "r"(addr));
}
#define CP_ASYNC16(dst, src) \
    asm volatile("cp.async.cg.shared.global [%0], [%1], 16;" :: "r"(dst), "l"(src))
#define CP_COMMIT() asm volatile("cp.async.commit_group;" ::: "memory")
#define CP_WAIT0()  asm volatile("cp.async.wait_group 0;" ::: "memory")

// ======================= CSR build =======================
__global__ void hist_kernel(const int* __restrict__ ei, const int* __restrict__ ea,
                            int* __restrict__ deg, int* __restrict__ code) {
    int e = blockIdx.x * 256 + threadIdx.x;
    if (e >= Ee) return;
    atomicAdd(&deg[__ldg(ei + Ee + e)], 1);
    int a0 = __ldg(ea + e * 3 + 0);
    int a1 = __ldg(ea + e * 3 + 1);
    int a2 = __ldg(ea + e * 3 + 2);
    code[e] = (a0 * 8 + a1) * 8 + a2;
}

// single-block warp-shfl scan -> rowptr (exclusive, shifted) + cursor copy
__global__ void scan_kernel(const int* __restrict__ deg,
                            int* __restrict__ rowptr, int* __restrict__ cursor) {
    __shared__ int wsum[32];
    __shared__ int carry_s;
    const int tid = threadIdx.x;           // 1024
    const int lane = tid & 31, w = tid >> 5;
    if (tid == 0) { carry_s = 0; rowptr[0] = 0; cursor[0] = 0; }
    __syncthreads();
    for (int base = 0; base < Nn; base += 1024) {
        int i = base + tid;
        int v = (i < Nn) ? deg[i] : 0;
#pragma unroll
        for (int o = 1; o < 32; o <<= 1) {
            int t = __shfl_up_sync(0xFFFFFFFFu, v, o);
            if (lane >= o) v += t;
        }
        if (lane == 31) wsum[w] = v;
        __syncthreads();
        if (w == 0) {
            int s = wsum[lane];
#pragma unroll
            for (int o = 1; o < 32; o <<= 1) {
                int t = __shfl_up_sync(0xFFFFFFFFu, s, o);
                if (lane >= o) s += t;
            }
            wsum[lane] = s;
        }
        __syncthreads();
        int off = carry_s + (w > 0 ? wsum[w - 1] : 0);
        if (i < Nn) { int incl = off + v; rowptr[i + 1] = incl; cursor[i + 1] = incl; }
        __syncthreads();
        if (tid == 0) carry_s += wsum[31];
        __syncthreads();
    }
}

// scatter edges into CSR order: contiguous srcs/codes/ews per dst node
__global__ void fill_kernel(const int* __restrict__ ei, const int* __restrict__ code,
                            const float* __restrict__ ew,
                            int* __restrict__ cursor,
                            int* __restrict__ srcs, int* __restrict__ codes,
                            float* __restrict__ ews) {
    int e = blockIdx.x * 256 + threadIdx.x;
    if (e >= Ee) return;
    int pos = atomicAdd(&cursor[__ldg(ei + Ee + e)], 1);
    srcs[pos]  = __ldg(ei + e);
    codes[pos] = __ldg(code + e);
    ews[pos]   = __ldg(ew + e);
}

// esum[l][c][d] = sum_f be[l][f][a_f][d], all layers
__global__ void esum_kernel(const float* __restrict__ be, float* __restrict__ esum) {
    int idx = blockIdx.x * 256 + threadIdx.x;   // < 5*512*128
    if (idx >= 5 * 512 * 128) return;
    int l = idx / (512 * 128), r = idx - l * (512 * 128);
    int c = r >> 7, d = r & 127;
    int a0 = c >> 6, a1 = (c >> 3) & 7, a2 = c & 7;
    const float* b = be + (size_t)l * 3 * 8 * 128;
    esum[idx] = __ldg(b + a0 * 128 + d) + __ldg(b + (8 + a1) * 128 + d)
              + __ldg(b + (16 + a2) * 128 + d);
}

// ======================= small kernels =======================
__global__ void init_h_kernel(const int* __restrict__ x,
                              const float* __restrict__ ae,
                              float* __restrict__ h) {
    int idx = blockIdx.x * blockDim.x + threadIdx.x;
    if (idx >= Nn * 128) return;
    int n = idx >> 7, d = idx & 127;
    float s = 0.f;
#pragma unroll
    for (int f = 0; f < 9; f++) {
        int xi = __ldg(x + n * 9 + f);
        s += __ldg(ae + (((size_t)(f * 120 + xi)) << 7) + d);
    }
    h[idx] = s;
}

// warp-per-node gather aggregation over CSR-ordered edge arrays.
__global__ void __launch_bounds__(256) edge_agg_kernel(
    const float* __restrict__ src_mat, const float* __restrict__ sc,
    const float* __restrict__ esum,
    const int* __restrict__ rowptr,
    const int* __restrict__ srcs, const int* __restrict__ codes,
    const float* __restrict__ ews, float* __restrict__ agg)
{
    __shared__ float ssc[128], ssh[128];
    if (sc && threadIdx.x < 128) {
        ssc[threadIdx.x] = sc[threadIdx.x];
        ssh[threadIdx.x] = sc[128 + threadIdx.x];
    }
    __syncthreads();

    int node = (blockIdx.x * 256 + threadIdx.x) >> 5;
    int lane = threadIdx.x & 31;
    int d0 = lane * 4;
    const bool fuse = sc != nullptr;
    float c0, c1, c2, c3, s0, s1, s2, s3;
    if (fuse) {
        c0 = ssc[d0]; c1 = ssc[d0 + 1]; c2 = ssc[d0 + 2]; c3 = ssc[d0 + 3];
        s0 = ssh[d0]; s1 = ssh[d0 + 1]; s2 = ssh[d0 + 2]; s3 = ssh[d0 + 3];
    }

    float a0 = 0.f, a1 = 0.f, a2 = 0.f, a3 = 0.f;
    int beg = __ldg(rowptr + node), end = __ldg(rowptr + node + 1);
    for (int i = beg; i < end; i++) {
        int src  = __ldg(srcs + i);
        int cd   = __ldg(codes + i);
        float w  = __ldg(ews + i);
        float4 hv = *(const float4*)(src_mat + (size_t)src * 128 + d0);
        if (fuse) {
            hv.x = fmaxf(fmaf(c0, hv.x, s0), 0.f);
            hv.y = fmaxf(fmaf(c1, hv.y, s1), 0.f);
            hv.z = fmaxf(fmaf(c2, hv.z, s2), 0.f);
            hv.w = fmaxf(fmaf(c3, hv.w, s3), 0.f);
        }
        const float4 ev = *(const float4*)(esum + (size_t)cd * 128 + d0);
        a0 = fmaf(fmaxf(hv.x + ev.x, 0.f), w, a0);
        a1 = fmaf(fmaxf(hv.y + ev.y, 0.f), w, a1);
        a2 = fmaf(fmaxf(hv.z + ev.z, 0.f), w, a2);
        a3 = fmaf(fmaxf(hv.w + ev.w, 0.f), w, a3);
    }
    *(float4*)(agg + (size_t)node * 128 + d0) = make_float4(a0, a1, a2, a3);
}

// all-layer weight transpose+split
__global__ void transpose_all_kernel(const float* __restrict__ W,
                                     __nv_bfloat16* __restrict__ Wt_hi,
                                     __nv_bfloat16* __restrict__ Wt_lo,
                                     int K, int NC) {
    int idx = blockIdx.x * 256 + threadIdx.x;
    int per = K * NC;
    if (idx >= 5 * per) return;
    int l = idx / per, r = idx - l * per;
    int n = r / K, k = r - n * K;
    float w = __ldg(W + (size_t)l * per + (size_t)k * NC + n);
    __nv_bfloat16 hi = __float2bfloat16(w);
    Wt_hi[idx] = hi;
    Wt_lo[idx] = __float2bfloat16(w - __bfloat162float(hi));
}

__global__ void finalize_bn(float* __restrict__ stats,
                            const float* __restrict__ g,
                            const float* __restrict__ bt,
                            float* __restrict__ scsh, int Cc) {
    int c = blockIdx.x * blockDim.x + threadIdx.x;
    if (c >= Cc) return;
    const float inv = 1.0f / (float)Nn;
    float mu  = stats[c] * inv;
    float var = stats[Cc + c] * inv - mu * mu;
    float sc  = __ldg(g + c) * rsqrtf(var + 1e-5f);
    scsh[c]      = sc;
    scsh[Cc + c] = fmaf(-mu, sc, __ldg(bt + c));
    stats[c] = 0.f;
    stats[Cc + c] = 0.f;
}

__global__ void apply_bn(const float* __restrict__ t2,
                         const float* __restrict__ scsh,
                         float* __restrict__ outp) {
    int idx = blockIdx.x * blockDim.x + threadIdx.x;
    if (idx >= Nn * 128) return;
    int c = idx & 127;
    outp[idx] = fmaf(scsh[c], t2[idx], scsh[128 + c]);
}

// ======================= pipelined bf16 hi/lo mma GEMM =======================
// MODE 0: X = (1+eps)*A + A2
// MODE 1: X = relu(sc[k]*A + sh[k])
// MODE 2: X = (1+eps)*relu(sc[k]*A + sh[k]) + A2
template <int K, int NC, int MODE>
__global__ void __launch_bounds__(256, 2) mma_gemm(
    const float* __restrict__ A, const float* __restrict__ A2,
    const float* __restrict__ epsp, int layer,
    const float* __restrict__ scsh,
    const __nv_bfloat16* __restrict__ Wt_hi, const __nv_bfloat16* __restrict__ Wt_lo,
    const float* __restrict__ bias,
    float* __restrict__ C, float* __restrict__ stats)
{
    constexpr int CHUNKS = K / 32;
    constexpr int STG = 40960;
    constexpr int AH = 0, AL = 10240, BH = 20480, BL = 30720;

    extern __shared__ char dsm[];
    __shared__ float s_sum[128];
    __shared__ float s_sq[128];

    uint32_t sb;
    asm("{ .reg .u64 t; cvta.to.shared.u64 t, %1; cvt.u32.u64 %0, t; }" : "=r"(sb) : "l"(dsm));

    const int tid  = threadIdx.x;
    const int wid  = tid >> 5, lane = tid & 31;
    const int g    = lane >> 2, t4 = lane & 3;
    const int wm   = wid & 3;
    const int wn   = wid >> 2;
    const int rowBase = blockIdx.x * 128;
    const int colBase = blockIdx.y * 128;

    if (tid < 128) { s_sum[tid] = 0.f; s_sq[tid] = 0.f; }

    float alpha = 1.0f;
    if (MODE != 1) alpha = 1.0f + __ldg(epsp + layer);
    const float* shv = scsh + K;

    const int lr  = tid >> 1;
    const int lk  = (tid & 1) * 16;
    const int lkb = (tid & 1) * 32;

    const int aoff = (wm * 32 + ((lane >> 3) & 1) * 8 + (lane & 7)) * 80 + (lane >> 4) * 16;
    const int boff = (wn * 64 + (lane >> 4) * 8 + (lane & 7)) * 80 + ((lane >> 3) & 1) * 16;

    float acc[2][8][4];
#pragma unroll
    for (int mt = 0; mt < 2; mt++)
#pragma unroll
        for (int nt = 0; nt < 8; nt++)
#pragma unroll
            for (int j = 0; j < 4; j++) acc[mt][nt][j] = 0.f;

    const int rg = rowBase + lr;
    const bool rv = rg < Nn;

    float4 pre[4];
    auto loadA = [&](int c) {
        const float* Ap = A + (size_t)rg * K + c * 32 + lk;
#pragma unroll
        for (int q = 0; q < 4; q++) {
            float4 v = make_float4(0.f, 0.f, 0.f, 0.f);
            if (rv) {
                float4 av = *(const float4*)(Ap + q * 4);
                int kg = c * 32 + lk + q * 4;
                if (MODE == 0) {
                    const float4 gv = *(const float4*)(A2 + (size_t)rg * K + kg);
                    v.x = fmaf(alpha, av.x, gv.x);
                    v.y = fmaf(alpha, av.y, gv.y);
                    v.z = fmaf(alpha, av.z, gv.z);
                    v.w = fmaf(alpha, av.w, gv.w);
                } else if (MODE == 1) {
                    v.x = fmaxf(fmaf(__ldg(scsh + kg + 0), av.x, __ldg(shv + kg + 0)), 0.f);
                    v.y = fmaxf(fmaf(__ldg(scsh + kg + 1), av.y, __ldg(shv + kg + 1)), 0.f);
                    v.z = fmaxf(fmaf(__ldg(scsh + kg + 2), av.z, __ldg(shv + kg + 2)), 0.f);
                    v.w = fmaxf(fmaf(__ldg(scsh + kg + 3), av.w, __ldg(shv + kg + 3)), 0.f);
                } else {
                    const float4 gv = *(const float4*)(A2 + (size_t)rg * K + kg);
                    float t0 = fmaxf(fmaf(__ldg(scsh + kg + 0), av.x, __ldg(shv + kg + 0)), 0.f);
                    float t1 = fmaxf(fmaf(__ldg(scsh + kg + 1), av.y, __ldg(shv + kg + 1)), 0.f);
                    float t2v = fmaxf(fmaf(__ldg(scsh + kg + 2), av.z, __ldg(shv + kg + 2)), 0.f);
                    float t3 = fmaxf(fmaf(__ldg(scsh + kg + 3), av.w, __ldg(shv + kg + 3)), 0.f);
                    v.x = fmaf(alpha, t0, gv.x);
                    v.y = fmaf(alpha, t1, gv.y);
                    v.z = fmaf(alpha, t2v, gv.z);
                    v.w = fmaf(alpha, t3, gv.w);
                }
            }
            pre[q] = v;
        }
    };
    auto cpasyncB = [&](int c, int stage) {
        const int n = colBase + lr;
        const __nv_bfloat16* Wh = Wt_hi + (size_t)n * K + c * 32 + lk;
        const __nv_bfloat16* Wl = Wt_lo + (size_t)n * K + c * 32 + lk;
        uint32_t dh = sb + stage * STG + BH + lr * 80 + lkb;
        uint32_t dl = sb + stage * STG + BL + lr * 80 + lkb;
        CP_ASYNC16(dh, Wh);
        CP_ASYNC16(dh + 16, Wh + 8);
        CP_ASYNC16(dl, Wl);
        CP_ASYNC16(dl + 16, Wl + 8);
    };
    auto storeA = [&](int stage) {
        uint32_t hi_d[8], lo_d[8];
#pragma unroll
        for (int q = 0; q < 4; q++) {
            float4 v = pre[q];
            __nv_bfloat162 h0 = __floats2bfloat162_rn(v.x, v.y);
            __nv_bfloat162 h1 = __floats2bfloat162_rn(v.z, v.w);
            float rx = v.x - __bfloat162float(h0.x);
            float ry = v.y - __bfloat162float(h0.y);
            float rz = v.z - __bfloat162float(h1.x);
            float rw = v.w - __bfloat162float(h1.y);
            __nv_bfloat162 l0 = __floats2bfloat162_rn(rx, ry);
            __nv_bfloat162 l1 = __floats2bfloat162_rn(rz, rw);
            hi_d[q * 2 + 0] = *(uint32_t*)&h0;
            hi_d[q * 2 + 1] = *(uint32_t*)&h1;
            lo_d[q * 2 + 0] = *(uint32_t*)&l0;
            lo_d[q * 2 + 1] = *(uint32_t*)&l1;
        }
        char* ah = dsm + stage * STG + AH + lr * 80 + lkb;
        char* al = dsm + stage * STG + AL + lr * 80 + lkb;
        *(uint4*)(ah)      = make_uint4(hi_d[0], hi_d[1], hi_d[2], hi_d[3]);
        *(uint4*)(ah + 16) = make_uint4(hi_d[4], hi_d[5], hi_d[6], hi_d[7]);
        *(uint4*)(al)      = make_uint4(lo_d[0], lo_d[1], lo_d[2], lo_d[3]);
        *(uint4*)(al + 16) = make_uint4(lo_d[4], lo_d[5], lo_d[6], lo_d[7]);
    };

    loadA(0);
    cpasyncB(0, 0);
    CP_COMMIT();
    storeA(0);
    CP_WAIT0();
    __syncthreads();

    for (int c = 0; c < CHUNKS; c++) {
        const int cur = c & 1, nxt = (c + 1) & 1;
        const bool more = (c + 1) < CHUNKS;
        if (more) {
            loadA(c + 1);
            cpasyncB(c + 1, nxt);
            CP_COMMIT();
        }

        const uint32_t base = sb + cur * STG;
#pragma unroll
        for (int ks = 0; ks < 2; ks++) {
            const int kb = ks * 32;
            uint32_t ah[2][4], al2[2][4];
#pragma unroll
            for (int mt = 0; mt < 2; mt++) {
                ldsm4(base + AH + aoff + mt * 1280 + kb, ah[mt]);
                ldsm4(base + AL + aoff + mt * 1280 + kb, al2[mt]);
            }
#pragma unroll
            for (int p = 0; p < 4; p++) {
                uint32_t bh[4], bl[4];
                ldsm4(base + BH + boff + p * 1280 + kb, bh);
                ldsm4(base + BL + boff + p * 1280 + kb, bl);
#pragma unroll
                for (int mt = 0; mt < 2; mt++) {
                    mma_bf16(acc[mt][2 * p],     al2[mt], bh[0], bh[1]);
                    mma_bf16(acc[mt][2 * p + 1], al2[mt], bh[2], bh[3]);
                }
#pragma unroll
                for (int mt = 0; mt < 2; mt++) {
                    mma_bf16(acc[mt][2 * p],     ah[mt], bl[0], bl[1]);
                    mma_bf16(acc[mt][2 * p + 1], ah[mt], bl[2], bl[3]);
                }
#pragma unroll
                for (int mt = 0; mt < 2; mt++) {
                    mma_bf16(acc[mt][2 * p],     ah[mt], bh[0], bh[1]);
                    mma_bf16(acc[mt][2 * p + 1], ah[mt], bh[2], bh[3]);
                }
            }
        }

        if (more) storeA(nxt);
        CP_WAIT0();
        __syncthreads();
    }

    // ---- epilogue ----
#pragma unroll
    for (int nt = 0; nt < 8; nt++) {
        int cl = wn * 64 + nt * 8 + t4 * 2;
        float b0 = __ldg(bias + colBase + cl);
        float b1 = __ldg(bias + colBase + cl + 1);
        float cs0 = 0.f, cq0 = 0.f, cs1 = 0.f, cq1 = 0.f;
#pragma unroll
        for (int mt = 0; mt < 2; mt++) {
            int r0 = rowBase + wm * 32 + mt * 16 + g;
#pragma unroll
            for (int half = 0; half < 2; half++) {
                int rr = r0 + half * 8;
                float v0 = acc[mt][nt][half * 2] + b0;
                float v1 = acc[mt][nt][half * 2 + 1] + b1;
                if (rr < Nn) {
                    *(float2*)(C + (size_t)rr * NC + colBase + cl) = make_float2(v0, v1);
                    cs0 += v0; cq0 += v0 * v0;
                    cs1 += v1; cq1 += v1 * v1;
                }
            }
        }
#pragma unroll
        for (int o = 4; o <= 16; o <<= 1) {
            cs0 += __shfl_xor_sync(0xFFFFFFFFu, cs0, o);
            cq0 += __shfl_xor_sync(0xFFFFFFFFu, cq0, o);
            cs1 += __shfl_xor_sync(0xFFFFFFFFu, cs1, o);
            cq1 += __shfl_xor_sync(0xFFFFFFFFu, cq1, o);
        }
        if (g == 0) {
            atomicAdd(&s_sum[cl], cs0);
            atomicAdd(&s_sq[cl], cq0);
            atomicAdd(&s_sum[cl + 1], cs1);
            atomicAdd(&s_sq[cl + 1], cq1);
        }
    }
    __syncthreads();
    if (tid < 128) {
        atomicAdd(&stats[colBase + tid],      s_sum[tid]);
        atomicAdd(&stats[NC + colBase + tid], s_sq[tid]);
    }
}

// ======================= launch =======================
extern "C" void kernel_launch(void* const* d_in, const int* in_sizes, int n_in,
                              void* d_out, int out_size) {
    const int*   x    = (const int*)d_in[0];
    const int*   ei   = (const int*)d_in[1];
    const int*   ea   = (const int*)d_in[2];
    const float* ew   = (const float*)d_in[3];
    const float* ae   = (const float*)d_in[4];
    const float* be   = (const float*)d_in[5];
    const float* eps  = (const float*)d_in[6];
    const float* W1   = (const float*)d_in[7];
    const float* b1   = (const float*)d_in[8];
    const float* g1   = (const float*)d_in[9];
    const float* bt1  = (const float*)d_in[10];
    const float* W2   = (const float*)d_in[11];
    const float* b2   = (const float*)d_in[12];
    const float* go   = (const float*)d_in[13];
    const float* bto  = (const float*)d_in[14];
    float* out = (float*)d_out;

    float *h, *agg, *t1, *t2, *stats, *sc1, *sc2, *esum, *ews;
    __nv_bfloat16 *wt1h, *wt1l, *wt2h, *wt2l;
    int *deg, *rowptr, *cursor, *srcs, *codes, *code;
    cudaGetSymbolAddress((void**)&h,      g_h);
    cudaGetSymbolAddress((void**)&agg,    g_agg);
    cudaGetSymbolAddress((void**)&t1,     g_t1);
    cudaGetSymbolAddress((void**)&t2,     g_t2);
    cudaGetSymbolAddress((void**)&wt1h,   g_wt1_hi);
    cudaGetSymbolAddress((void**)&wt1l,   g_wt1_lo);
    cudaGetSymbolAddress((void**)&wt2h,   g_wt2_hi);
    cudaGetSymbolAddress((void**)&wt2l,   g_wt2_lo);
    cudaGetSymbolAddress((void**)&stats,  g_stats);
    cudaGetSymbolAddress((void**)&sc1,    g_sc1);
    cudaGetSymbolAddress((void**)&sc2,    g_sc2);
    cudaGetSymbolAddress((void**)&deg,    g_deg);
    cudaGetSymbolAddress((void**)&rowptr, g_rowptr);
    cudaGetSymbolAddress((void**)&cursor, g_cursor);
    cudaGetSymbolAddress((void**)&srcs,   g_srcs);
    cudaGetSymbolAddress((void**)&codes,  g_codes);
    cudaGetSymbolAddress((void**)&ews,    g_ews);
    cudaGetSymbolAddress((void**)&code,   g_code);
    cudaGetSymbolAddress((void**)&esum,   g_esum);
    float* st1 = stats;
    float* st2 = stats + 512;

    const int DSMEM = 2 * 40960;
    cudaFuncSetAttribute(mma_gemm<128, 256, 0>,
                         cudaFuncAttributeMaxDynamicSharedMemorySize, DSMEM);
    cudaFuncSetAttribute(mma_gemm<128, 256, 2>,
                         cudaFuncAttributeMaxDynamicSharedMemorySize, DSMEM);
    cudaFuncSetAttribute(mma_gemm<256, 128, 1>,
                         cudaFuncAttributeMaxDynamicSharedMemorySize, DSMEM);

    const int elem_blocks = (Nn * 128 + 255) / 256;
    const int gemm_blocks = (Nn + 127) / 128;
    const int edge_blocks = (Ee + 255) / 256;

    // ---- one-time (per call) setup ----
    cudaMemsetAsync(deg, 0, Nn * sizeof(int));
    cudaMemsetAsync(stats, 0, 768 * sizeof(float));
    init_h_kernel<<<elem_blocks, 256>>>(x, ae, h);
    transpose_all_kernel<<<(5 * 128 * 256 + 255) / 256, 256>>>(W1, wt1h, wt1l, 128, 256);
    transpose_all_kernel<<<(5 * 128 * 256 + 255) / 256, 256>>>(W2, wt2h, wt2l, 256, 128);
    esum_kernel<<<(5 * 512 * 128 + 255) / 256, 256>>>(be, esum);
    hist_kernel<<<edge_blocks, 256>>>(ei, ea, deg, code);
    scan_kernel<<<1, 1024>>>(deg, rowptr, cursor);
    fill_kernel<<<edge_blocks, 256>>>(ei, code, ew, cursor, srcs, codes, ews);

    for (int l = 0; l < Ll; l++) {
        const size_t wo = (size_t)l * 128 * 256;
        const float* es = esum + (size_t)l * 512 * 128;

        dim3 grid1(gemm_blocks, 2);
        if (l == 0) {
            edge_agg_kernel<<<Nn / 8, 256>>>(h, (const float*)nullptr, es,
                                             rowptr, srcs, codes, ews, agg);
            mma_gemm<128, 256, 0><<<grid1, 256, DSMEM>>>(
                h, agg, eps, l, (const float*)nullptr,
                wt1h + wo, wt1l + wo, b1 + l * 256, t1, st1);
        } else {
            edge_agg_kernel<<<Nn / 8, 256>>>(t2, sc2, es,
                                             rowptr, srcs, codes, ews, agg);
            mma_gemm<128, 256, 2><<<grid1, 256, DSMEM>>>(
                t2, agg, eps, l, sc2,
                wt1h + wo, wt1l + wo, b1 + l * 256, t1, st1);
        }
        finalize_bn<<<1, 256>>>(st1, g1 + l * 256, bt1 + l * 256, sc1, 256);

        dim3 grid2(gemm_blocks, 1);
        mma_gemm<256, 128, 1><<<grid2, 256, DSMEM>>>(
            t1, (const float*)nullptr, (const float*)nullptr, 0, sc1,
            wt2h + wo, wt2l + wo, b2 + l * 128, t2, st2);
        finalize_bn<<<1, 128>>>(st2, go + l * 128, bto + l * 128, sc2, 128);
    }
    apply_bn<<<elem_blocks, 256>>>(t2, sc2, out);
}

// round 14
// speedup vs baseline: 2.6255x; 1.0028x over previous
#include <cuda_runtime.h>
#include <cuda_bf16.h>
#include <cstdint>
#include <cstddef>

#define Nn 100000
#define Ee 500000
#define Ll 5

// -------- scratch (device globals: allocation-free) --------
__device__ __align__(16) float g_h[(size_t)Nn * 128];
__device__ __align__(16) float g_agg[(size_t)Nn * 128];
__device__ __align__(16) float g_t1[(size_t)Nn * 256];
__device__ __align__(16) float g_t2[(size_t)Nn * 128];
__device__ __align__(16) __nv_bfloat16 g_wt1_hi[5 * 256 * 128];
__device__ __align__(16) __nv_bfloat16 g_wt1_lo[5 * 256 * 128];
__device__ __align__(16) __nv_bfloat16 g_wt2_hi[5 * 128 * 256];
__device__ __align__(16) __nv_bfloat16 g_wt2_lo[5 * 128 * 256];
__device__ float g_stats[768];
__device__ float g_sc1[512];
__device__ float g_sc2[256];
// CSR scratch
__device__ int g_deg[Nn];
__device__ int g_rowptr[Nn + 1];
__device__ int g_cursor[Nn + 1];
__device__ int g_srcs[Ee];
__device__ int g_codes[Ee];
__device__ float g_ews[Ee];
__device__ int g_code[Ee];
__device__ __align__(16) float g_esum[5 * 512 * 128];

// ======================= PTX helpers =======================
__device__ __forceinline__ void mma_bf16(float* c, const uint32_t* a, uint32_t b0, uint32_t b1) {
    asm volatile(
        "mma.sync.aligned.m16n8k16.row.col.f32.bf16.bf16.f32 "
        "{%0,%1,%2,%3}, {%4,%5,%6,%7}, {%8,%9}, {%0,%1,%2,%3};"
        : "+f"(c[0]), "+f"(c[1]), "+f"(c[2]), "+f"(c[3])
        : "r"(a[0]), "r"(a[1]), "r"(a[2]), "r"(a[3]), "r"(b0), "r"(b1));
}
__device__ __forceinline__ void ldsm4(uint32_t addr, uint32_t* r) {
    asm volatile("ldmatrix.sync.aligned.m8n8.x4.shared.b16 {%0,%1,%2,%3}, [%4];"
                 : "=r"(r[0]), "=r"(r[1]), "=r"(r[2]), "=r"(r[3]) : "r"(addr));
}
#define CP_ASYNC16(dst, src) \
    asm volatile("cp.async.cg.shared.global [%0], [%1], 16;" :: "r"(dst), "l"(src))
#define CP_COMMIT() asm volatile("cp.async.commit_group;" ::: "memory")
#define CP_WAIT0()  asm volatile("cp.async.wait_group 0;" ::: "memory")

// ======================= fused setup =======================
// One launch: init h, zero deg/stats, transpose+split W1/W2, build esum.
__global__ void setup_kernel(const int* __restrict__ x, const float* __restrict__ ae,
                             const float* __restrict__ W1, const float* __restrict__ W2,
                             const float* __restrict__ be,
                             float* __restrict__ h,
                             __nv_bfloat16* __restrict__ wt1h, __nv_bfloat16* __restrict__ wt1l,
                             __nv_bfloat16* __restrict__ wt2h, __nv_bfloat16* __restrict__ wt2l,
                             float* __restrict__ esum,
                             int* __restrict__ deg, float* __restrict__ stats) {
    int idx = blockIdx.x * 256 + threadIdx.x;
    if (idx < Nn * 128) {
        int n = idx >> 7, d = idx & 127;
        float s = 0.f;
#pragma unroll
        for (int f = 0; f < 9; f++) {
            int xi = __ldg(x + n * 9 + f);
            s += __ldg(ae + (((size_t)(f * 120 + xi)) << 7) + d);
        }
        h[idx] = s;
    }
    if (idx < Nn) deg[idx] = 0;
    if (idx < 768) stats[idx] = 0.f;
    if (idx < 5 * 128 * 256) {   // W1: K=128, NC=256
        const int per = 128 * 256;
        int l = idx / per, r = idx - l * per;
        int n = r / 128, k = r - n * 128;
        float w = __ldg(W1 + (size_t)l * per + (size_t)k * 256 + n);
        __nv_bfloat16 hi = __float2bfloat16(w);
        wt1h[idx] = hi;
        wt1l[idx] = __float2bfloat16(w - __bfloat162float(hi));
        // W2: K=256, NC=128
        int n2 = r / 256, k2 = r - n2 * 256;
        float w2 = __ldg(W2 + (size_t)l * per + (size_t)k2 * 128 + n2);
        __nv_bfloat16 hi2 = __float2bfloat16(w2);
        wt2h[idx] = hi2;
        wt2l[idx] = __float2bfloat16(w2 - __bfloat162float(hi2));
    }
    if (idx < 5 * 512 * 128) {
        int l = idx / (512 * 128), r = idx - l * (512 * 128);
        int c = r >> 7, d = r & 127;
        int a0 = c >> 6, a1 = (c >> 3) & 7, a2 = c & 7;
        const float* b = be + (size_t)l * 3 * 8 * 128;
        esum[idx] = __ldg(b + a0 * 128 + d) + __ldg(b + (8 + a1) * 128 + d)
                  + __ldg(b + (16 + a2) * 128 + d);
    }
}

// ======================= CSR build =======================
__global__ void hist_kernel(const int* __restrict__ ei, const int* __restrict__ ea,
                            int* __restrict__ deg, int* __restrict__ code) {
    int e = blockIdx.x * 256 + threadIdx.x;
    if (e >= Ee) return;
    atomicAdd(&deg[__ldg(ei + Ee + e)], 1);
    int a0 = __ldg(ea + e * 3 + 0);
    int a1 = __ldg(ea + e * 3 + 1);
    int a2 = __ldg(ea + e * 3 + 2);
    code[e] = (a0 * 8 + a1) * 8 + a2;
}

__global__ void scan_kernel(const int* __restrict__ deg,
                            int* __restrict__ rowptr, int* __restrict__ cursor) {
    __shared__ int wsum[32];
    __shared__ int carry_s;
    const int tid = threadIdx.x;           // 1024
    const int lane = tid & 31, w = tid >> 5;
    if (tid == 0) { carry_s = 0; rowptr[0] = 0; cursor[0] = 0; }
    __syncthreads();
    for (int base = 0; base < Nn; base += 1024) {
        int i = base + tid;
        int v = (i < Nn) ? deg[i] : 0;
#pragma unroll
        for (int o = 1; o < 32; o <<= 1) {
            int t = __shfl_up_sync(0xFFFFFFFFu, v, o);
            if (lane >= o) v += t;
        }
        if (lane == 31) wsum[w] = v;
        __syncthreads();
        if (w == 0) {
            int s = wsum[lane];
#pragma unroll
            for (int o = 1; o < 32; o <<= 1) {
                int t = __shfl_up_sync(0xFFFFFFFFu, s, o);
                if (lane >= o) s += t;
            }
            wsum[lane] = s;
        }
        __syncthreads();
        int off = carry_s + (w > 0 ? wsum[w - 1] : 0);
        if (i < Nn) { int incl = off + v; rowptr[i + 1] = incl; cursor[i + 1] = incl; }
        __syncthreads();
        if (tid == 0) carry_s += wsum[31];
        __syncthreads();
    }
}

__global__ void fill_kernel(const int* __restrict__ ei, const int* __restrict__ code,
                            const float* __restrict__ ew,
                            int* __restrict__ cursor,
                            int* __restrict__ srcs, int* __restrict__ codes,
                            float* __restrict__ ews) {
    int e = blockIdx.x * 256 + threadIdx.x;
    if (e >= Ee) return;
    int pos = atomicAdd(&cursor[__ldg(ei + Ee + e)], 1);
    srcs[pos]  = __ldg(ei + e);
    codes[pos] = __ldg(code + e);
    ews[pos]   = __ldg(ew + e);
}

// ======================= small kernels =======================
// warp-per-node gather aggregation over CSR-ordered edge arrays.
__global__ void __launch_bounds__(256) edge_agg_kernel(
    const float* __restrict__ src_mat, const float* __restrict__ sc,
    const float* __restrict__ esum,
    const int* __restrict__ rowptr,
    const int* __restrict__ srcs, const int* __restrict__ codes,
    const float* __restrict__ ews, float* __restrict__ agg)
{
    __shared__ float ssc[128], ssh[128];
    if (sc && threadIdx.x < 128) {
        ssc[threadIdx.x] = sc[threadIdx.x];
        ssh[threadIdx.x] = sc[128 + threadIdx.x];
    }
    __syncthreads();

    int node = (blockIdx.x * 256 + threadIdx.x) >> 5;
    int lane = threadIdx.x & 31;
    int d0 = lane * 4;
    const bool fuse = sc != nullptr;
    float c0, c1, c2, c3, s0, s1, s2, s3;
    if (fuse) {
        c0 = ssc[d0]; c1 = ssc[d0 + 1]; c2 = ssc[d0 + 2]; c3 = ssc[d0 + 3];
        s0 = ssh[d0]; s1 = ssh[d0 + 1]; s2 = ssh[d0 + 2]; s3 = ssh[d0 + 3];
    }

    float a0 = 0.f, a1 = 0.f, a2 = 0.f, a3 = 0.f;
    int beg = __ldg(rowptr + node), end = __ldg(rowptr + node + 1);
    for (int i = beg; i < end; i++) {
        int src  = __ldg(srcs + i);
        int cd   = __ldg(codes + i);
        float w  = __ldg(ews + i);
        float4 hv = *(const float4*)(src_mat + (size_t)src * 128 + d0);
        if (fuse) {
            hv.x = fmaxf(fmaf(c0, hv.x, s0), 0.f);
            hv.y = fmaxf(fmaf(c1, hv.y, s1), 0.f);
            hv.z = fmaxf(fmaf(c2, hv.z, s2), 0.f);
            hv.w = fmaxf(fmaf(c3, hv.w, s3), 0.f);
        }
        const float4 ev = *(const float4*)(esum + (size_t)cd * 128 + d0);
        a0 = fmaf(fmaxf(hv.x + ev.x, 0.f), w, a0);
        a1 = fmaf(fmaxf(hv.y + ev.y, 0.f), w, a1);
        a2 = fmaf(fmaxf(hv.z + ev.z, 0.f), w, a2);
        a3 = fmaf(fmaxf(hv.w + ev.w, 0.f), w, a3);
    }
    *(float4*)(agg + (size_t)node * 128 + d0) = make_float4(a0, a1, a2, a3);
}

__global__ void finalize_bn(float* __restrict__ stats,
                            const float* __restrict__ g,
                            const float* __restrict__ bt,
                            float* __restrict__ scsh, int Cc) {
    int c = blockIdx.x * blockDim.x + threadIdx.x;
    if (c >= Cc) return;
    const float inv = 1.0f / (float)Nn;
    float mu  = stats[c] * inv;
    float var = stats[Cc + c] * inv - mu * mu;
    float sc  = __ldg(g + c) * rsqrtf(var + 1e-5f);
    scsh[c]      = sc;
    scsh[Cc + c] = fmaf(-mu, sc, __ldg(bt + c));
    stats[c] = 0.f;
    stats[Cc + c] = 0.f;
}

__global__ void apply_bn(const float* __restrict__ t2,
                         const float* __restrict__ scsh,
                         float* __restrict__ outp) {
    int idx = blockIdx.x * blockDim.x + threadIdx.x;
    if (idx >= Nn * 128) return;
    int c = idx & 127;
    outp[idx] = fmaf(scsh[c], t2[idx], scsh[128 + c]);
}

// ======================= pipelined bf16 hi/lo mma GEMM =======================
// MODE 0: X = (1+eps)*A + A2
// MODE 1: X = relu(sc[k]*A + sh[k])
// MODE 2: X = (1+eps)*relu(sc[k]*A + sh[k]) + A2
template <int K, int NC, int MODE>
__global__ void __launch_bounds__(256, 2) mma_gemm(
    const float* __restrict__ A, const float* __restrict__ A2,
    const float* __restrict__ epsp, int layer,
    const float* __restrict__ scsh,
    const __nv_bfloat16* __restrict__ Wt_hi, const __nv_bfloat16* __restrict__ Wt_lo,
    const float* __restrict__ bias,
    float* __restrict__ C, float* __restrict__ stats)
{
    constexpr int CHUNKS = K / 32;
    constexpr int STG = 40960;
    constexpr int AH = 0, AL = 10240, BH = 20480, BL = 30720;

    extern __shared__ char dsm[];
    __shared__ float s_sum[128];
    __shared__ float s_sq[128];

    uint32_t sb;
    asm("{ .reg .u64 t; cvta.to.shared.u64 t, %1; cvt.u32.u64 %0, t; }" : "=r"(sb) : "l"(dsm));

    const int tid  = threadIdx.x;
    const int wid  = tid >> 5, lane = tid & 31;
    const int g    = lane >> 2, t4 = lane & 3;
    const int wm   = wid & 3;
    const int wn   = wid >> 2;
    const int rowBase = blockIdx.x * 128;
    const int colBase = blockIdx.y * 128;

    if (tid < 128) { s_sum[tid] = 0.f; s_sq[tid] = 0.f; }

    float alpha = 1.0f;
    if (MODE != 1) alpha = 1.0f + __ldg(epsp + layer);
    const float* shv = scsh + K;

    const int lr  = tid >> 1;
    const int lk  = (tid & 1) * 16;
    const int lkb = (tid & 1) * 32;

    const int aoff = (wm * 32 + ((lane >> 3) & 1) * 8 + (lane & 7)) * 80 + (lane >> 4) * 16;
    const int boff = (wn * 64 + (lane >> 4) * 8 + (lane & 7)) * 80 + ((lane >> 3) & 1) * 16;

    float acc[2][8][4];
#pragma unroll
    for (int mt = 0; mt < 2; mt++)
#pragma unroll
        for (int nt = 0; nt < 8; nt++)
#pragma unroll
            for (int j = 0; j < 4; j++) acc[mt][nt][j] = 0.f;

    const int rg = rowBase + lr;
    const bool rv = rg < Nn;

    float4 pre[4];
    auto loadA = [&](int c) {
        const float* Ap = A + (size_t)rg * K + c * 32 + lk;
#pragma unroll
        for (int q = 0; q < 4; q++) {
            float4 v = make_float4(0.f, 0.f, 0.f, 0.f);
            if (rv) {
                float4 av = *(const float4*)(Ap + q * 4);
                int kg = c * 32 + lk + q * 4;
                if (MODE == 0) {
                    const float4 gv = *(const float4*)(A2 + (size_t)rg * K + kg);
                    v.x = fmaf(alpha, av.x, gv.x);
                    v.y = fmaf(alpha, av.y, gv.y);
                    v.z = fmaf(alpha, av.z, gv.z);
                    v.w = fmaf(alpha, av.w, gv.w);
                } else if (MODE == 1) {
                    v.x = fmaxf(fmaf(__ldg(scsh + kg + 0), av.x, __ldg(shv + kg + 0)), 0.f);
                    v.y = fmaxf(fmaf(__ldg(scsh + kg + 1), av.y, __ldg(shv + kg + 1)), 0.f);
                    v.z = fmaxf(fmaf(__ldg(scsh + kg + 2), av.z, __ldg(shv + kg + 2)), 0.f);
                    v.w = fmaxf(fmaf(__ldg(scsh + kg + 3), av.w, __ldg(shv + kg + 3)), 0.f);
                } else {
                    const float4 gv = *(const float4*)(A2 + (size_t)rg * K + kg);
                    float t0 = fmaxf(fmaf(__ldg(scsh + kg + 0), av.x, __ldg(shv + kg + 0)), 0.f);
                    float t1 = fmaxf(fmaf(__ldg(scsh + kg + 1), av.y, __ldg(shv + kg + 1)), 0.f);
                    float t2v = fmaxf(fmaf(__ldg(scsh + kg + 2), av.z, __ldg(shv + kg + 2)), 0.f);
                    float t3 = fmaxf(fmaf(__ldg(scsh + kg + 3), av.w, __ldg(shv + kg + 3)), 0.f);
                    v.x = fmaf(alpha, t0, gv.x);
                    v.y = fmaf(alpha, t1, gv.y);
                    v.z = fmaf(alpha, t2v, gv.z);
                    v.w = fmaf(alpha, t3, gv.w);
                }
            }
            pre[q] = v;
        }
    };
    auto cpasyncB = [&](int c, int stage) {
        const int n = colBase + lr;
        const __nv_bfloat16* Wh = Wt_hi + (size_t)n * K + c * 32 + lk;
        const __nv_bfloat16* Wl = Wt_lo + (size_t)n * K + c * 32 + lk;
        uint32_t dh = sb + stage * STG + BH + lr * 80 + lkb;
        uint32_t dl = sb + stage * STG + BL + lr * 80 + lkb;
        CP_ASYNC16(dh, Wh);
        CP_ASYNC16(dh + 16, Wh + 8);
        CP_ASYNC16(dl, Wl);
        CP_ASYNC16(dl + 16, Wl + 8);
    };
    auto storeA = [&](int stage) {
        uint32_t hi_d[8], lo_d[8];
#pragma unroll
        for (int q = 0; q < 4; q++) {
            float4 v = pre[q];
            __nv_bfloat162 h0 = __floats2bfloat162_rn(v.x, v.y);
            __nv_bfloat162 h1 = __floats2bfloat162_rn(v.z, v.w);
            float rx = v.x - __bfloat162float(h0.x);
            float ry = v.y - __bfloat162float(h0.y);
            float rz = v.z - __bfloat162float(h1.x);
            float rw = v.w - __bfloat162float(h1.y);
            __nv_bfloat162 l0 = __floats2bfloat162_rn(rx, ry);
            __nv_bfloat162 l1 = __floats2bfloat162_rn(rz, rw);
            hi_d[q * 2 + 0] = *(uint32_t*)&h0;
            hi_d[q * 2 + 1] = *(uint32_t*)&h1;
            lo_d[q * 2 + 0] = *(uint32_t*)&l0;
            lo_d[q * 2 + 1] = *(uint32_t*)&l1;
        }
        char* ah = dsm + stage * STG + AH + lr * 80 + lkb;
        char* al = dsm + stage * STG + AL + lr * 80 + lkb;
        *(uint4*)(ah)      = make_uint4(hi_d[0], hi_d[1], hi_d[2], hi_d[3]);
        *(uint4*)(ah + 16) = make_uint4(hi_d[4], hi_d[5], hi_d[6], hi_d[7]);
        *(uint4*)(al)      = make_uint4(lo_d[0], lo_d[1], lo_d[2], lo_d[3]);
        *(uint4*)(al + 16) = make_uint4(lo_d[4], lo_d[5], lo_d[6], lo_d[7]);
    };

    loadA(0);
    cpasyncB(0, 0);
    CP_COMMIT();
    storeA(0);
    CP_WAIT0();
    __syncthreads();

    for (int c = 0; c < CHUNKS; c++) {
        const int cur = c & 1, nxt = (c + 1) & 1;
        const bool more = (c + 1) < CHUNKS;
        if (more) {
            loadA(c + 1);
            cpasyncB(c + 1, nxt);
            CP_COMMIT();
        }

        const uint32_t base = sb + cur * STG;
#pragma unroll
        for (int ks = 0; ks < 2; ks++) {
            const int kb = ks * 32;
            uint32_t ah[2][4], al2[2][4];
#pragma unroll
            for (int mt = 0; mt < 2; mt++) {
                ldsm4(base + AH + aoff + mt * 1280 + kb, ah[mt]);
                ldsm4(base + AL + aoff + mt * 1280 + kb, al2[mt]);
            }
            // n-group pairs: 24 MMAs over 8 distinct accumulators per pair,
            // term-major -> dependent MMAs to the same acc are 8 issues apart
#pragma unroll
            for (int pp = 0; pp < 2; pp++) {
                uint32_t bh[2][4], bl[2][4];
                ldsm4(base + BH + boff + (2 * pp    ) * 1280 + kb, bh[0]);
                ldsm4(base + BH + boff + (2 * pp + 1) * 1280 + kb, bh[1]);
                ldsm4(base + BL + boff + (2 * pp    ) * 1280 + kb, bl[0]);
                ldsm4(base + BL + boff + (2 * pp + 1) * 1280 + kb, bl[1]);
#pragma unroll
                for (int q = 0; q < 2; q++) {
                    int p = 2 * pp + q;
#pragma unroll
                    for (int mt = 0; mt < 2; mt++) {
                        mma_bf16(acc[mt][2 * p],     al2[mt], bh[q][0], bh[q][1]);
                        mma_bf16(acc[mt][2 * p + 1], al2[mt], bh[q][2], bh[q][3]);
                    }
                }
#pragma unroll
                for (int q = 0; q < 2; q++) {
                    int p = 2 * pp + q;
#pragma unroll
                    for (int mt = 0; mt < 2; mt++) {
                        mma_bf16(acc[mt][2 * p],     ah[mt], bl[q][0], bl[q][1]);
                        mma_bf16(acc[mt][2 * p + 1], ah[mt], bl[q][2], bl[q][3]);
                    }
                }
#pragma unroll
                for (int q = 0; q < 2; q++) {
                    int p = 2 * pp + q;
#pragma unroll
                    for (int mt = 0; mt < 2; mt++) {
                        mma_bf16(acc[mt][2 * p],     ah[mt], bh[q][0], bh[q][1]);
                        mma_bf16(acc[mt][2 * p + 1], ah[mt], bh[q][2], bh[q][3]);
                    }
                }
            }
        }

        if (more) storeA(nxt);
        CP_WAIT0();
        __syncthreads();
    }

    // ---- epilogue ----
#pragma unroll
    for (int nt = 0; nt < 8; nt++) {
        int cl = wn * 64 + nt * 8 + t4 * 2;
        float b0 = __ldg(bias + colBase + cl);
        float b1 = __ldg(bias + colBase + cl + 1);
        float cs0 = 0.f, cq0 = 0.f, cs1 = 0.f, cq1 = 0.f;
#pragma unroll
        for (int mt = 0; mt < 2; mt++) {
            int r0 = rowBase + wm * 32 + mt * 16 + g;
#pragma unroll
            for (int half = 0; half < 2; half++) {
                int rr = r0 + half * 8;
                float v0 = acc[mt][nt][half * 2] + b0;
                float v1 = acc[mt][nt][half * 2 + 1] + b1;
                if (rr < Nn) {
                    *(float2*)(C + (size_t)rr * NC + colBase + cl) = make_float2(v0, v1);
                    cs0 += v0; cq0 += v0 * v0;
                    cs1 += v1; cq1 += v1 * v1;
                }
            }
        }
#pragma unroll
        for (int o = 4; o <= 16; o <<= 1) {
            cs0 += __shfl_xor_sync(0xFFFFFFFFu, cs0, o);
            cq0 += __shfl_xor_sync(0xFFFFFFFFu, cq0, o);
            cs1 += __shfl_xor_sync(0xFFFFFFFFu, cs1, o);
            cq1 += __shfl_xor_sync(0xFFFFFFFFu, cq1, o);
        }
        if (g == 0) {
            atomicAdd(&s_sum[cl], cs0);
            atomicAdd(&s_sq[cl], cq0);
            atomicAdd(&s_sum[cl + 1], cs1);
            atomicAdd(&s_sq[cl + 1], cq1);
        }
    }
    __syncthreads();
    if (tid < 128) {
        atomicAdd(&stats[colBase + tid],      s_sum[tid]);
        atomicAdd(&stats[NC + colBase + tid], s_sq[tid]);
    }
}

// ======================= launch =======================
extern "C" void kernel_launch(void* const* d_in, const int* in_sizes, int n_in,
                              void* d_out, int out_size) {
    const int*   x    = (const int*)d_in[0];
    const int*   ei   = (const int*)d_in[1];
    const int*   ea   = (const int*)d_in[2];
    const float* ew   = (const float*)d_in[3];
    const float* ae   = (const float*)d_in[4];
    const float* be   = (const float*)d_in[5];
    const float* eps  = (const float*)d_in[6];
    const float* W1   = (const float*)d_in[7];
    const float* b1   = (const float*)d_in[8];
    const float* g1   = (const float*)d_in[9];
    const float* bt1  = (const float*)d_in[10];
    const float* W2   = (const float*)d_in[11];
    const float* b2   = (const float*)d_in[12];
    const float* go   = (const float*)d_in[13];
    const float* bto  = (const float*)d_in[14];
    float* out = (float*)d_out;

    float *h, *agg, *t1, *t2, *stats, *sc1, *sc2, *esum, *ews;
    __nv_bfloat16 *wt1h, *wt1l, *wt2h, *wt2l;
    int *deg, *rowptr, *cursor, *srcs, *codes, *code;
    cudaGetSymbolAddress((void**)&h,      g_h);
    cudaGetSymbolAddress((void**)&agg,    g_agg);
    cudaGetSymbolAddress((void**)&t1,     g_t1);
    cudaGetSymbolAddress((void**)&t2,     g_t2);
    cudaGetSymbolAddress((void**)&wt1h,   g_wt1_hi);
    cudaGetSymbolAddress((void**)&wt1l,   g_wt1_lo);
    cudaGetSymbolAddress((void**)&wt2h,   g_wt2_hi);
    cudaGetSymbolAddress((void**)&wt2l,   g_wt2_lo);
    cudaGetSymbolAddress((void**)&stats,  g_stats);
    cudaGetSymbolAddress((void**)&sc1,    g_sc1);
    cudaGetSymbolAddress((void**)&sc2,    g_sc2);
    cudaGetSymbolAddress((void**)&deg,    g_deg);
    cudaGetSymbolAddress((void**)&rowptr, g_rowptr);
    cudaGetSymbolAddress((void**)&cursor, g_cursor);
    cudaGetSymbolAddress((void**)&srcs,   g_srcs);
    cudaGetSymbolAddress((void**)&codes,  g_codes);
    cudaGetSymbolAddress((void**)&ews,    g_ews);
    cudaGetSymbolAddress((void**)&code,   g_code);
    cudaGetSymbolAddress((void**)&esum,   g_esum);
    float* st1 = stats;
    float* st2 = stats + 512;

    const int DSMEM = 2 * 40960;
    cudaFuncSetAttribute(mma_gemm<128, 256, 0>,
                         cudaFuncAttributeMaxDynamicSharedMemorySize, DSMEM);
    cudaFuncSetAttribute(mma_gemm<128, 256, 2>,
                         cudaFuncAttributeMaxDynamicSharedMemorySize, DSMEM);
    cudaFuncSetAttribute(mma_gemm<256, 128, 1>,
                         cudaFuncAttributeMaxDynamicSharedMemorySize, DSMEM);

    const int elem_blocks = (Nn * 128 + 255) / 256;
    const int gemm_blocks = (Nn + 127) / 128;
    const int edge_blocks = (Ee + 255) / 256;

    // ---- setup: launches 1..4; edge_agg=5, first gemm1=6 (ncu -s 5 -c 1 slot) ----
    setup_kernel<<<elem_blocks, 256>>>(x, ae, W1, W2, be, h,
                                       wt1h, wt1l, wt2h, wt2l, esum, deg, stats);
    hist_kernel<<<edge_blocks, 256>>>(ei, ea, deg, code);
    scan_kernel<<<1, 1024>>>(deg, rowptr, cursor);
    fill_kernel<<<edge_blocks, 256>>>(ei, code, ew, cursor, srcs, codes, ews);

    for (int l = 0; l < Ll; l++) {
        const size_t wo = (size_t)l * 128 * 256;
        const float* es = esum + (size_t)l * 512 * 128;

        dim3 grid1(gemm_blocks, 2);
        if (l == 0) {
            edge_agg_kernel<<<Nn / 8, 256>>>(h, (const float*)nullptr, es,
                                             rowptr, srcs, codes, ews, agg);
            mma_gemm<128, 256, 0><<<grid1, 256, DSMEM>>>(
                h, agg, eps, l, (const float*)nullptr,
                wt1h + wo, wt1l + wo, b1 + l * 256, t1, st1);
        } else {
            edge_agg_kernel<<<Nn / 8, 256>>>(t2, sc2, es,
                                             rowptr, srcs, codes, ews, agg);
            mma_gemm<128, 256, 2><<<grid1, 256, DSMEM>>>(
                t2, agg, eps, l, sc2,
                wt1h + wo, wt1l + wo, b1 + l * 256, t1, st1);
        }
        finalize_bn<<<1, 256>>>(st1, g1 + l * 256, bt1 + l * 256, sc1, 256);

        dim3 grid2(gemm_blocks, 1);
        mma_gemm<256, 128, 1><<<grid2, 256, DSMEM>>>(
            t1, (const float*)nullptr, (const float*)nullptr, 0, sc1,
            wt2h + wo, wt2l + wo, b2 + l * 128, t2, st2);
        finalize_bn<<<1, 128>>>(st2, go + l * 128, bto + l * 128, sc2, 128);
    }
    apply_bn<<<elem_blocks, 256>>>(t2, sc2, out);
}